// round 1
// baseline (speedup 1.0000x reference)
#include <cuda_runtime.h>
#include <math.h>

#define D_    1024
#define A_    64
#define TOPK_ 32
#define B_    2
#define S_    4096
#define N_    (B_ * S_)   /* 8192 tokens */
#define DI_   4096

// ---------------------------------------------------------------------------
// Scratch (device globals: allocation-free per harness rules)
// ---------------------------------------------------------------------------
__device__ float g_x1[N_ * D_];
__device__ float g_xa[N_ * D_];     // mixed (v) for TM, mixed (k) for CM
__device__ float g_xb[N_ * D_];     // mixed (r) for TM and CM
__device__ float g_v[N_ * D_];
__device__ float g_r[N_ * D_];
__device__ float g_Q[N_ * A_];
__device__ float g_Kp[N_ * A_];
__device__ float g_Vsa[N_ * D_];
__device__ float g_scores[(long long)B_ * S_ * S_];   // 128 MB
__device__ float g_attnpre[N_ * D_];
__device__ float g_rkv[N_ * D_];
__device__ float g_xmid[N_ * D_];
__device__ float g_x2[N_ * D_];
__device__ float g_kcm[(long long)N_ * DI_];          // 128 MB
__device__ float g_r2[N_ * D_];

// ---------------------------------------------------------------------------
// RMSNorm: out = w * x / (||x||/sqrt(D) + eps)       one block per row
// ---------------------------------------------------------------------------
__global__ __launch_bounds__(256)
void rmsnorm_kernel(const float* __restrict__ x, const float* __restrict__ w,
                    float* __restrict__ out)
{
    int n   = blockIdx.x;
    int tid = threadIdx.x;
    const float4* xr = (const float4*)(x + (long)n * D_);
    float4 xv = xr[tid];
    float ss = xv.x * xv.x + xv.y * xv.y + xv.z * xv.z + xv.w * xv.w;
    #pragma unroll
    for (int off = 16; off; off >>= 1) ss += __shfl_xor_sync(0xffffffffu, ss, off);
    __shared__ float warpss[8];
    if ((tid & 31) == 0) warpss[tid >> 5] = ss;
    __syncthreads();
    __shared__ float s_scale;
    if (tid == 0) {
        float tot = 0.f;
        #pragma unroll
        for (int i = 0; i < 8; i++) tot += warpss[i];
        float norm = sqrtf(tot / (float)D_);
        s_scale = 1.f / (norm + 1e-8f);
    }
    __syncthreads();
    float sc = s_scale;
    float4 wv = ((const float4*)w)[tid];
    float4 ov;
    ov.x = xv.x * wv.x * sc; ov.y = xv.y * wv.y * sc;
    ov.z = xv.z * wv.z * sc; ov.w = xv.w * wv.w * sc;
    ((float4*)(out + (long)n * D_))[tid] = ov;
}

// ---------------------------------------------------------------------------
// Token-shift mix: oA = x*mA + prev(x)*(1-mA);  oB = x*mB + prev(x)*(1-mB)
// ---------------------------------------------------------------------------
__global__ __launch_bounds__(256)
void mix2_kernel(const float* __restrict__ x,
                 const float* __restrict__ mA, const float* __restrict__ mB,
                 float* __restrict__ oA, float* __restrict__ oB)
{
    int n = blockIdx.x;
    int s = n & (S_ - 1);
    int prev = (s == 0) ? n : n - 1;
    int tid = threadIdx.x;
    float4 cur = ((const float4*)(x + (long)n    * D_))[tid];
    float4 pv  = ((const float4*)(x + (long)prev * D_))[tid];
    float4 ma = ((const float4*)mA)[tid];
    float4 mb = ((const float4*)mB)[tid];
    float4 oa, ob;
    oa.x = cur.x * ma.x + pv.x * (1.f - ma.x);
    oa.y = cur.y * ma.y + pv.y * (1.f - ma.y);
    oa.z = cur.z * ma.z + pv.z * (1.f - ma.z);
    oa.w = cur.w * ma.w + pv.w * (1.f - ma.w);
    ob.x = cur.x * mb.x + pv.x * (1.f - mb.x);
    ob.y = cur.y * mb.y + pv.y * (1.f - mb.y);
    ob.z = cur.z * mb.z + pv.z * (1.f - mb.z);
    ob.w = cur.w * mb.w + pv.w * (1.f - mb.w);
    ((float4*)(oA + (long)n * D_))[tid] = oa;
    ((float4*)(oB + (long)n * D_))[tid] = ob;
}

// ---------------------------------------------------------------------------
// Generic NT GEMM:  C[n,m] = sum_k A[n,k] * Bw[m,k]   (+ fused epilogues)
// 128x128 tile, BK=8, 256 threads, 8x8 micro-tile / thread.
// ---------------------------------------------------------------------------
#define BM 128
#define BN 128
#define BK 8

#define EPI_NONE  0
#define EPI_BIAS  1
#define EPI_SCALE 2
#define EPI_RELU2 3
#define EPI_RKV   4   /* sigmoid(E1) * (acc + bias + E0) */
#define EPI_ADD   5   /* acc + E0                        */
#define EPI_CMFIN 6   /* E0 + sigmoid(E1) * acc          */

__device__ __forceinline__ float sigmoidf_(float x) { return 1.f / (1.f + expf(-x)); }

template<int EPI>
__global__ __launch_bounds__(256)
void gemm_nt(const float* __restrict__ A, const float* __restrict__ Bw,
             const float* __restrict__ bias, const float* __restrict__ E0,
             const float* __restrict__ E1, float* __restrict__ C,
             int N, int M, int K,
             long long sA, long long sB, long long sC, float scale)
{
    A  += (long long)blockIdx.z * sA;
    Bw += (long long)blockIdx.z * sB;
    C  += (long long)blockIdx.z * sC;

    __shared__ float As[BK][BM];
    __shared__ float Bs[BK][BN];

    int tid  = threadIdx.x;
    int row0 = blockIdx.y * BM;   // N dim
    int col0 = blockIdx.x * BN;   // M dim

    int lr = tid >> 1;            // 0..127 row within tile
    int lk = (tid & 1) * 4;       // 0 or 4 in K

    int tx = tid & 15;            // 0..15 (col groups)
    int ty = tid >> 4;            // 0..15 (row groups)

    float acc[8][8];
    #pragma unroll
    for (int i = 0; i < 8; i++)
        #pragma unroll
        for (int j = 0; j < 8; j++) acc[i][j] = 0.f;

    const float* Aptr = A + (long long)(row0 + lr) * K + lk;
    bool bvalid = (col0 + lr) < M;
    const float* Bptr = Bw + (long long)(col0 + lr) * K + lk;

    float4 av = *(const float4*)(Aptr);
    float4 bv = bvalid ? *(const float4*)(Bptr) : make_float4(0.f, 0.f, 0.f, 0.f);

    for (int k0 = 0; k0 < K; k0 += BK) {
        __syncthreads();
        As[lk + 0][lr] = av.x; As[lk + 1][lr] = av.y;
        As[lk + 2][lr] = av.z; As[lk + 3][lr] = av.w;
        Bs[lk + 0][lr] = bv.x; Bs[lk + 1][lr] = bv.y;
        Bs[lk + 2][lr] = bv.z; Bs[lk + 3][lr] = bv.w;
        __syncthreads();

        if (k0 + BK < K) {
            av = *(const float4*)(Aptr + k0 + BK);
            bv = bvalid ? *(const float4*)(Bptr + k0 + BK)
                        : make_float4(0.f, 0.f, 0.f, 0.f);
        }

        #pragma unroll
        for (int kk = 0; kk < BK; kk++) {
            float a[8], b[8];
            float4 t;
            t = *(const float4*)&As[kk][ty * 4];      a[0]=t.x; a[1]=t.y; a[2]=t.z; a[3]=t.w;
            t = *(const float4*)&As[kk][64 + ty * 4]; a[4]=t.x; a[5]=t.y; a[6]=t.z; a[7]=t.w;
            t = *(const float4*)&Bs[kk][tx * 4];      b[0]=t.x; b[1]=t.y; b[2]=t.z; b[3]=t.w;
            t = *(const float4*)&Bs[kk][64 + tx * 4]; b[4]=t.x; b[5]=t.y; b[6]=t.z; b[7]=t.w;
            #pragma unroll
            for (int i = 0; i < 8; i++)
                #pragma unroll
                for (int j = 0; j < 8; j++)
                    acc[i][j] += a[i] * b[j];
        }
    }

    #pragma unroll
    for (int i = 0; i < 8; i++) {
        int r = row0 + ((i < 4) ? (ty * 4 + i) : (60 + ty * 4 + i));
        #pragma unroll
        for (int j = 0; j < 8; j++) {
            int c = col0 + ((j < 4) ? (tx * 4 + j) : (60 + tx * 4 + j));
            if (c < M) {
                long long idx = (long long)r * M + c;
                float val = acc[i][j];
                float outv;
                if      (EPI == EPI_NONE)  outv = val;
                else if (EPI == EPI_BIAS)  outv = val + bias[c];
                else if (EPI == EPI_SCALE) outv = val * scale;
                else if (EPI == EPI_RELU2) { float u = fmaxf(val, 0.f); outv = u * u; }
                else if (EPI == EPI_RKV)   outv = sigmoidf_(E1[idx]) * (val + bias[c] + E0[idx]);
                else if (EPI == EPI_ADD)   outv = val + E0[idx];
                else /* EPI_CMFIN */       outv = E0[idx] + sigmoidf_(E1[idx]) * val;
                C[idx] = outv;
            }
        }
    }
}

// ---------------------------------------------------------------------------
// Top-k(32) + softmax + sparse V gather. One block per query.
// Scores live in registers (16/thread); 32x argmax extraction.
// ---------------------------------------------------------------------------
__global__ __launch_bounds__(256)
void topk_attn_kernel(const float* __restrict__ scores,
                      const float* __restrict__ V,
                      float* __restrict__ out)
{
    int q   = blockIdx.x;            // global query 0..8191
    int b   = q >> 12;               // q / S
    int qs  = q & (S_ - 1);
    int tid = threadIdx.x;
    const float* srow = scores + (long long)b * S_ * S_ + (long long)qs * S_;

    float s[16];
    #pragma unroll
    for (int i = 0; i < 16; i++) s[i] = srow[i * 256 + tid];

    __shared__ float wv[8];
    __shared__ int   wi[8];
    __shared__ float top_val[TOPK_];
    __shared__ int   top_idx[TOPK_];
    __shared__ int   s_win;

    const float NEG = -__int_as_float(0x7f800000);  // -inf

    for (int t = 0; t < TOPK_; t++) {
        float best = NEG; int bi = 0;
        #pragma unroll
        for (int i = 0; i < 16; i++)
            if (s[i] > best) { best = s[i]; bi = i; }
        int gidx = bi * 256 + tid;
        #pragma unroll
        for (int off = 16; off; off >>= 1) {
            float ov = __shfl_down_sync(0xffffffffu, best, off);
            int   oi = __shfl_down_sync(0xffffffffu, gidx, off);
            if (ov > best) { best = ov; gidx = oi; }
        }
        if ((tid & 31) == 0) { wv[tid >> 5] = best; wi[tid >> 5] = gidx; }
        __syncthreads();
        if (tid == 0) {
            float bb = wv[0]; int bbi = wi[0];
            #pragma unroll
            for (int w = 1; w < 8; w++)
                if (wv[w] > bb) { bb = wv[w]; bbi = wi[w]; }
            top_val[t] = bb; top_idx[t] = bbi; s_win = bbi;
        }
        __syncthreads();
        int win = s_win;
        if ((win & 255) == tid) s[win >> 8] = NEG;
    }

    __shared__ float wts[TOPK_];
    if (tid < 32) {
        float m = top_val[0];           // extracted in descending order
        float e = expf(top_val[tid] - m);
        float ssum = e;
        #pragma unroll
        for (int off = 16; off; off >>= 1)
            ssum += __shfl_xor_sync(0xffffffffu, ssum, off);
        wts[tid] = e / ssum;
    }
    __syncthreads();

    const float* Vb = V + (long long)b * S_ * D_;
    float4 accv = make_float4(0.f, 0.f, 0.f, 0.f);
    #pragma unroll
    for (int t = 0; t < TOPK_; t++) {
        float w = wts[t];
        float4 vr = *(const float4*)&Vb[(long long)top_idx[t] * D_ + tid * 4];
        accv.x += w * vr.x; accv.y += w * vr.y;
        accv.z += w * vr.z; accv.w += w * vr.w;
    }
    *(float4*)&out[(long long)q * D_ + tid * 4] = accv;
}

// ---------------------------------------------------------------------------
// Host launch
// ---------------------------------------------------------------------------
template <typename T>
static float* symaddr(T& sym)
{
    void* p = nullptr;
    cudaGetSymbolAddress(&p, sym);
    return (float*)p;
}

extern "C" void kernel_launch(void* const* d_in, const int* in_sizes, int n_in,
                              void* d_out, int out_size)
{
    const float* x         = (const float*)d_in[0];
    const float* norm1_w   = (const float*)d_in[1];
    /* d_in[2] tm_mix_k : dead (k branch unused in reference) */
    const float* tm_mix_v  = (const float*)d_in[3];
    const float* tm_mix_r  = (const float*)d_in[4];
    /* d_in[5] tm_key_w : dead */
    const float* tm_value_w = (const float*)d_in[6];
    const float* tm_recept_w= (const float*)d_in[7];
    const float* tm_out_w  = (const float*)d_in[8];
    const float* sa_q_w    = (const float*)d_in[9];
    const float* sa_q_b    = (const float*)d_in[10];
    const float* sa_k_w    = (const float*)d_in[11];
    const float* sa_k_b    = (const float*)d_in[12];
    const float* sa_v_w    = (const float*)d_in[13];
    const float* sa_v_b    = (const float*)d_in[14];
    const float* sa_o_w    = (const float*)d_in[15];
    const float* sa_o_b    = (const float*)d_in[16];
    const float* norm2_w   = (const float*)d_in[17];
    const float* cm_mix_k  = (const float*)d_in[18];
    const float* cm_mix_r  = (const float*)d_in[19];
    const float* cm_key_w  = (const float*)d_in[20];
    const float* cm_recept_w = (const float*)d_in[21];
    const float* cm_value_w  = (const float*)d_in[22];

    float* out = (float*)d_out;

    float* x1   = symaddr(g_x1);
    float* xa   = symaddr(g_xa);
    float* xb   = symaddr(g_xb);
    float* v    = symaddr(g_v);
    float* r    = symaddr(g_r);
    float* Q    = symaddr(g_Q);
    float* Kp   = symaddr(g_Kp);
    float* Vsa  = symaddr(g_Vsa);
    float* sc   = symaddr(g_scores);
    float* apre = symaddr(g_attnpre);
    float* rkv  = symaddr(g_rkv);
    float* xmid = symaddr(g_xmid);
    float* x2   = symaddr(g_x2);
    float* kcm  = symaddr(g_kcm);
    float* r2   = symaddr(g_r2);

    const int T = 256;

    // ---- time-mix branch ----
    rmsnorm_kernel<<<N_, T>>>(x, norm1_w, x1);
    mix2_kernel<<<N_, T>>>(x1, tm_mix_v, tm_mix_r, xa, xb);

    dim3 gDD(D_ / BN, N_ / BM, 1);              // (8, 64)
    gemm_nt<EPI_NONE><<<gDD, T>>>(xa, tm_value_w, nullptr, nullptr, nullptr, v,
                                  N_, D_, D_, 0, 0, 0, 0.f);
    gemm_nt<EPI_NONE><<<gDD, T>>>(xb, tm_recept_w, nullptr, nullptr, nullptr, r,
                                  N_, D_, D_, 0, 0, 0, 0.f);

    dim3 gA(1, N_ / BM, 1);                     // M=64 fits in one col tile
    gemm_nt<EPI_BIAS><<<gA, T>>>(x1, sa_q_w, sa_q_b, nullptr, nullptr, Q,
                                 N_, A_, D_, 0, 0, 0, 0.f);
    gemm_nt<EPI_BIAS><<<gA, T>>>(x1, sa_k_w, sa_k_b, nullptr, nullptr, Kp,
                                 N_, A_, D_, 0, 0, 0, 0.f);
    gemm_nt<EPI_BIAS><<<gDD, T>>>(x1, sa_v_w, sa_v_b, nullptr, nullptr, Vsa,
                                  N_, D_, D_, 0, 0, 0, 0.f);

    // scores[b] = Q[b] @ K[b]^T / sqrt(A)   (batched)
    dim3 gS(S_ / BN, S_ / BM, B_);              // (32, 32, 2)
    gemm_nt<EPI_SCALE><<<gS, T>>>(Q, Kp, nullptr, nullptr, nullptr, sc,
                                  S_, S_, A_,
                                  (long long)S_ * A_, (long long)S_ * A_,
                                  (long long)S_ * S_, 0.125f);

    topk_attn_kernel<<<N_, T>>>(sc, Vsa, apre);

    // rkv = sigmoid(r) * (attn_pre @ o_w^T + o_b + v)
    gemm_nt<EPI_RKV><<<gDD, T>>>(apre, sa_o_w, sa_o_b, v, r, rkv,
                                 N_, D_, D_, 0, 0, 0, 0.f);
    // x_mid = x + rkv @ tm_out_w^T
    gemm_nt<EPI_ADD><<<gDD, T>>>(rkv, tm_out_w, nullptr, x, nullptr, xmid,
                                 N_, D_, D_, 0, 0, 0, 0.f);

    // ---- channel-mix branch ----
    rmsnorm_kernel<<<N_, T>>>(xmid, norm2_w, x2);
    mix2_kernel<<<N_, T>>>(x2, cm_mix_k, cm_mix_r, xa, xb);

    dim3 gDI(DI_ / BN, N_ / BM, 1);             // (32, 64)
    gemm_nt<EPI_RELU2><<<gDI, T>>>(xa, cm_key_w, nullptr, nullptr, nullptr, kcm,
                                   N_, DI_, D_, 0, 0, 0, 0.f);
    gemm_nt<EPI_NONE><<<gDD, T>>>(xb, cm_recept_w, nullptr, nullptr, nullptr, r2,
                                  N_, D_, D_, 0, 0, 0, 0.f);
    // out = x_mid + sigmoid(r2) * (kcm @ cm_value_w^T)
    gemm_nt<EPI_CMFIN><<<gDD, T>>>(kcm, cm_value_w, nullptr, xmid, r2, out,
                                   N_, D_, DI_, 0, 0, 0, 0.f);
}

// round 2
// speedup vs baseline: 1.0004x; 1.0004x over previous
#include <cuda_runtime.h>
#include <math.h>

#define D_    1024
#define A_    64
#define TOPK_ 32
#define B_    2
#define S_    4096
#define N_    (B_ * S_)   /* 8192 tokens */
#define DI_   4096

// ---------------------------------------------------------------------------
// Scratch (device globals: allocation-free per harness rules)
// ---------------------------------------------------------------------------
__device__ float g_x1[N_ * D_];
__device__ float g_xa[N_ * D_];     // mixed (v) for TM, mixed (k) for CM
__device__ float g_xb[N_ * D_];     // mixed (r) for TM and CM
__device__ float g_v[N_ * D_];
__device__ float g_r[N_ * D_];
__device__ float g_Q[N_ * A_];
__device__ float g_Kp[N_ * A_];
__device__ float g_Vsa[N_ * D_];
__device__ float g_scores[(long long)B_ * S_ * S_];   // 128 MB
__device__ float g_attnpre[N_ * D_];
__device__ float g_rkv[N_ * D_];
__device__ float g_xmid[N_ * D_];
__device__ float g_x2[N_ * D_];
__device__ float g_kcm[(long long)N_ * DI_];          // 128 MB
__device__ float g_r2[N_ * D_];

// ---------------------------------------------------------------------------
// RMSNorm: out = w * x / (||x||/sqrt(D) + eps)       one block per row
// ---------------------------------------------------------------------------
__global__ __launch_bounds__(256)
void rmsnorm_kernel(const float* __restrict__ x, const float* __restrict__ w,
                    float* __restrict__ out)
{
    int n   = blockIdx.x;
    int tid = threadIdx.x;
    const float4* xr = (const float4*)(x + (long)n * D_);
    float4 xv = xr[tid];
    float ss = xv.x * xv.x + xv.y * xv.y + xv.z * xv.z + xv.w * xv.w;
    #pragma unroll
    for (int off = 16; off; off >>= 1) ss += __shfl_xor_sync(0xffffffffu, ss, off);
    __shared__ float warpss[8];
    if ((tid & 31) == 0) warpss[tid >> 5] = ss;
    __syncthreads();
    __shared__ float s_scale;
    if (tid == 0) {
        float tot = 0.f;
        #pragma unroll
        for (int i = 0; i < 8; i++) tot += warpss[i];
        float norm = sqrtf(tot / (float)D_);
        s_scale = 1.f / (norm + 1e-8f);
    }
    __syncthreads();
    float sc = s_scale;
    float4 wv = ((const float4*)w)[tid];
    float4 ov;
    ov.x = xv.x * wv.x * sc; ov.y = xv.y * wv.y * sc;
    ov.z = xv.z * wv.z * sc; ov.w = xv.w * wv.w * sc;
    ((float4*)(out + (long)n * D_))[tid] = ov;
}

// ---------------------------------------------------------------------------
// Token-shift mix: oA = x*mA + prev(x)*(1-mA);  oB = x*mB + prev(x)*(1-mB)
// ---------------------------------------------------------------------------
__global__ __launch_bounds__(256)
void mix2_kernel(const float* __restrict__ x,
                 const float* __restrict__ mA, const float* __restrict__ mB,
                 float* __restrict__ oA, float* __restrict__ oB)
{
    int n = blockIdx.x;
    int s = n & (S_ - 1);
    int prev = (s == 0) ? n : n - 1;
    int tid = threadIdx.x;
    float4 cur = ((const float4*)(x + (long)n    * D_))[tid];
    float4 pv  = ((const float4*)(x + (long)prev * D_))[tid];
    float4 ma = ((const float4*)mA)[tid];
    float4 mb = ((const float4*)mB)[tid];
    float4 oa, ob;
    oa.x = cur.x * ma.x + pv.x * (1.f - ma.x);
    oa.y = cur.y * ma.y + pv.y * (1.f - ma.y);
    oa.z = cur.z * ma.z + pv.z * (1.f - ma.z);
    oa.w = cur.w * ma.w + pv.w * (1.f - ma.w);
    ob.x = cur.x * mb.x + pv.x * (1.f - mb.x);
    ob.y = cur.y * mb.y + pv.y * (1.f - mb.y);
    ob.z = cur.z * mb.z + pv.z * (1.f - mb.z);
    ob.w = cur.w * mb.w + pv.w * (1.f - mb.w);
    ((float4*)(oA + (long)n * D_))[tid] = oa;
    ((float4*)(oB + (long)n * D_))[tid] = ob;
}

// ---------------------------------------------------------------------------
// Generic NT GEMM:  C[n,m] = sum_k A[n,k] * Bw[m,k]   (+ fused epilogues)
// 128x128 tile, BK=8, 256 threads, 8x8 micro-tile / thread.
// ---------------------------------------------------------------------------
#define BM 128
#define BN 128
#define BK 8

#define EPI_NONE  0
#define EPI_BIAS  1
#define EPI_SCALE 2
#define EPI_RELU2 3
#define EPI_RKV   4   /* sigmoid(E1) * (acc + bias + E0) */
#define EPI_ADD   5   /* acc + E0                        */
#define EPI_CMFIN 6   /* E0 + sigmoid(E1) * acc          */

__device__ __forceinline__ float sigmoidf_(float x) { return 1.f / (1.f + expf(-x)); }

template<int EPI>
__global__ __launch_bounds__(256)
void gemm_nt(const float* __restrict__ A, const float* __restrict__ Bw,
             const float* __restrict__ bias, const float* __restrict__ E0,
             const float* __restrict__ E1, float* __restrict__ C,
             int N, int M, int K,
             long long sA, long long sB, long long sC, float scale)
{
    A  += (long long)blockIdx.z * sA;
    Bw += (long long)blockIdx.z * sB;
    C  += (long long)blockIdx.z * sC;

    __shared__ float As[BK][BM];
    __shared__ float Bs[BK][BN];

    int tid  = threadIdx.x;
    int row0 = blockIdx.y * BM;   // N dim
    int col0 = blockIdx.x * BN;   // M dim

    int lr = tid >> 1;            // 0..127 row within tile
    int lk = (tid & 1) * 4;       // 0 or 4 in K

    int tx = tid & 15;            // 0..15 (col groups)
    int ty = tid >> 4;            // 0..15 (row groups)

    float acc[8][8];
    #pragma unroll
    for (int i = 0; i < 8; i++)
        #pragma unroll
        for (int j = 0; j < 8; j++) acc[i][j] = 0.f;

    const float* Aptr = A + (long long)(row0 + lr) * K + lk;
    bool bvalid = (col0 + lr) < M;
    const float* Bptr = Bw + (long long)(col0 + lr) * K + lk;

    float4 av = *(const float4*)(Aptr);
    float4 bv = bvalid ? *(const float4*)(Bptr) : make_float4(0.f, 0.f, 0.f, 0.f);

    for (int k0 = 0; k0 < K; k0 += BK) {
        __syncthreads();
        As[lk + 0][lr] = av.x; As[lk + 1][lr] = av.y;
        As[lk + 2][lr] = av.z; As[lk + 3][lr] = av.w;
        Bs[lk + 0][lr] = bv.x; Bs[lk + 1][lr] = bv.y;
        Bs[lk + 2][lr] = bv.z; Bs[lk + 3][lr] = bv.w;
        __syncthreads();

        if (k0 + BK < K) {
            av = *(const float4*)(Aptr + k0 + BK);
            bv = bvalid ? *(const float4*)(Bptr + k0 + BK)
                        : make_float4(0.f, 0.f, 0.f, 0.f);
        }

        #pragma unroll
        for (int kk = 0; kk < BK; kk++) {
            float a[8], b[8];
            float4 t;
            t = *(const float4*)&As[kk][ty * 4];      a[0]=t.x; a[1]=t.y; a[2]=t.z; a[3]=t.w;
            t = *(const float4*)&As[kk][64 + ty * 4]; a[4]=t.x; a[5]=t.y; a[6]=t.z; a[7]=t.w;
            t = *(const float4*)&Bs[kk][tx * 4];      b[0]=t.x; b[1]=t.y; b[2]=t.z; b[3]=t.w;
            t = *(const float4*)&Bs[kk][64 + tx * 4]; b[4]=t.x; b[5]=t.y; b[6]=t.z; b[7]=t.w;
            #pragma unroll
            for (int i = 0; i < 8; i++)
                #pragma unroll
                for (int j = 0; j < 8; j++)
                    acc[i][j] += a[i] * b[j];
        }
    }

    #pragma unroll
    for (int i = 0; i < 8; i++) {
        int r = row0 + ((i < 4) ? (ty * 4 + i) : (60 + ty * 4 + i));
        #pragma unroll
        for (int j = 0; j < 8; j++) {
            int c = col0 + ((j < 4) ? (tx * 4 + j) : (60 + tx * 4 + j));
            if (c < M) {
                long long idx = (long long)r * M + c;
                float val = acc[i][j];
                float outv;
                if      (EPI == EPI_NONE)  outv = val;
                else if (EPI == EPI_BIAS)  outv = val + bias[c];
                else if (EPI == EPI_SCALE) outv = val * scale;
                else if (EPI == EPI_RELU2) { float u = fmaxf(val, 0.f); outv = u * u; }
                else if (EPI == EPI_RKV)   outv = sigmoidf_(E1[idx]) * (val + bias[c] + E0[idx]);
                else if (EPI == EPI_ADD)   outv = val + E0[idx];
                else /* EPI_CMFIN */       outv = E0[idx] + sigmoidf_(E1[idx]) * val;
                C[idx] = outv;
            }
        }
    }
}

// ---------------------------------------------------------------------------
// Top-k(32) + softmax + sparse V gather. One block per query.
// Scores live in registers (16/thread); 32x argmax extraction.
// ---------------------------------------------------------------------------
__global__ __launch_bounds__(256)
void topk_attn_kernel(const float* __restrict__ scores,
                      const float* __restrict__ V,
                      float* __restrict__ out)
{
    int q   = blockIdx.x;            // global query 0..8191
    int b   = q >> 12;               // q / S
    int qs  = q & (S_ - 1);
    int tid = threadIdx.x;
    const float* srow = scores + (long long)b * S_ * S_ + (long long)qs * S_;

    float s[16];
    #pragma unroll
    for (int i = 0; i < 16; i++) s[i] = srow[i * 256 + tid];

    __shared__ float wv[8];
    __shared__ int   wi[8];
    __shared__ float top_val[TOPK_];
    __shared__ int   top_idx[TOPK_];
    __shared__ int   s_win;

    const float NEG = -__int_as_float(0x7f800000);  // -inf

    for (int t = 0; t < TOPK_; t++) {
        float best = NEG; int bi = 0;
        #pragma unroll
        for (int i = 0; i < 16; i++)
            if (s[i] > best) { best = s[i]; bi = i; }
        int gidx = bi * 256 + tid;
        #pragma unroll
        for (int off = 16; off; off >>= 1) {
            float ov = __shfl_down_sync(0xffffffffu, best, off);
            int   oi = __shfl_down_sync(0xffffffffu, gidx, off);
            if (ov > best) { best = ov; gidx = oi; }
        }
        if ((tid & 31) == 0) { wv[tid >> 5] = best; wi[tid >> 5] = gidx; }
        __syncthreads();
        if (tid == 0) {
            float bb = wv[0]; int bbi = wi[0];
            #pragma unroll
            for (int w = 1; w < 8; w++)
                if (wv[w] > bb) { bb = wv[w]; bbi = wi[w]; }
            top_val[t] = bb; top_idx[t] = bbi; s_win = bbi;
        }
        __syncthreads();
        int win = s_win;
        if ((win & 255) == tid) s[win >> 8] = NEG;
    }

    __shared__ float wts[TOPK_];
    if (tid < 32) {
        float m = top_val[0];           // extracted in descending order
        float e = expf(top_val[tid] - m);
        float ssum = e;
        #pragma unroll
        for (int off = 16; off; off >>= 1)
            ssum += __shfl_xor_sync(0xffffffffu, ssum, off);
        wts[tid] = e / ssum;
    }
    __syncthreads();

    const float* Vb = V + (long long)b * S_ * D_;
    float4 accv = make_float4(0.f, 0.f, 0.f, 0.f);
    #pragma unroll
    for (int t = 0; t < TOPK_; t++) {
        float w = wts[t];
        float4 vr = *(const float4*)&Vb[(long long)top_idx[t] * D_ + tid * 4];
        accv.x += w * vr.x; accv.y += w * vr.y;
        accv.z += w * vr.z; accv.w += w * vr.w;
    }
    *(float4*)&out[(long long)q * D_ + tid * 4] = accv;
}

// ---------------------------------------------------------------------------
// Host launch
// ---------------------------------------------------------------------------
template <typename T>
static float* symaddr(T& sym)
{
    void* p = nullptr;
    cudaGetSymbolAddress(&p, sym);
    return (float*)p;
}

extern "C" void kernel_launch(void* const* d_in, const int* in_sizes, int n_in,
                              void* d_out, int out_size)
{
    const float* x         = (const float*)d_in[0];
    const float* norm1_w   = (const float*)d_in[1];
    /* d_in[2] tm_mix_k : dead (k branch unused in reference) */
    const float* tm_mix_v  = (const float*)d_in[3];
    const float* tm_mix_r  = (const float*)d_in[4];
    /* d_in[5] tm_key_w : dead */
    const float* tm_value_w = (const float*)d_in[6];
    const float* tm_recept_w= (const float*)d_in[7];
    const float* tm_out_w  = (const float*)d_in[8];
    const float* sa_q_w    = (const float*)d_in[9];
    const float* sa_q_b    = (const float*)d_in[10];
    const float* sa_k_w    = (const float*)d_in[11];
    const float* sa_k_b    = (const float*)d_in[12];
    const float* sa_v_w    = (const float*)d_in[13];
    const float* sa_v_b    = (const float*)d_in[14];
    const float* sa_o_w    = (const float*)d_in[15];
    const float* sa_o_b    = (const float*)d_in[16];
    const float* norm2_w   = (const float*)d_in[17];
    const float* cm_mix_k  = (const float*)d_in[18];
    const float* cm_mix_r  = (const float*)d_in[19];
    const float* cm_key_w  = (const float*)d_in[20];
    const float* cm_recept_w = (const float*)d_in[21];
    const float* cm_value_w  = (const float*)d_in[22];

    float* out = (float*)d_out;

    float* x1   = symaddr(g_x1);
    float* xa   = symaddr(g_xa);
    float* xb   = symaddr(g_xb);
    float* v    = symaddr(g_v);
    float* r    = symaddr(g_r);
    float* Q    = symaddr(g_Q);
    float* Kp   = symaddr(g_Kp);
    float* Vsa  = symaddr(g_Vsa);
    float* sc   = symaddr(g_scores);
    float* apre = symaddr(g_attnpre);
    float* rkv  = symaddr(g_rkv);
    float* xmid = symaddr(g_xmid);
    float* x2   = symaddr(g_x2);
    float* kcm  = symaddr(g_kcm);
    float* r2   = symaddr(g_r2);

    const int T = 256;

    // ---- time-mix branch ----
    rmsnorm_kernel<<<N_, T>>>(x, norm1_w, x1);
    mix2_kernel<<<N_, T>>>(x1, tm_mix_v, tm_mix_r, xa, xb);

    dim3 gDD(D_ / BN, N_ / BM, 1);              // (8, 64)
    gemm_nt<EPI_NONE><<<gDD, T>>>(xa, tm_value_w, nullptr, nullptr, nullptr, v,
                                  N_, D_, D_, 0, 0, 0, 0.f);
    gemm_nt<EPI_NONE><<<gDD, T>>>(xb, tm_recept_w, nullptr, nullptr, nullptr, r,
                                  N_, D_, D_, 0, 0, 0, 0.f);

    dim3 gA(1, N_ / BM, 1);                     // M=64 fits in one col tile
    gemm_nt<EPI_BIAS><<<gA, T>>>(x1, sa_q_w, sa_q_b, nullptr, nullptr, Q,
                                 N_, A_, D_, 0, 0, 0, 0.f);
    gemm_nt<EPI_BIAS><<<gA, T>>>(x1, sa_k_w, sa_k_b, nullptr, nullptr, Kp,
                                 N_, A_, D_, 0, 0, 0, 0.f);
    gemm_nt<EPI_BIAS><<<gDD, T>>>(x1, sa_v_w, sa_v_b, nullptr, nullptr, Vsa,
                                  N_, D_, D_, 0, 0, 0, 0.f);

    // scores[b] = Q[b] @ K[b]^T / sqrt(A)   (batched)
    dim3 gS(S_ / BN, S_ / BM, B_);              // (32, 32, 2)
    gemm_nt<EPI_SCALE><<<gS, T>>>(Q, Kp, nullptr, nullptr, nullptr, sc,
                                  S_, S_, A_,
                                  (long long)S_ * A_, (long long)S_ * A_,
                                  (long long)S_ * S_, 0.125f);

    topk_attn_kernel<<<N_, T>>>(sc, Vsa, apre);

    // rkv = sigmoid(r) * (attn_pre @ o_w^T + o_b + v)
    gemm_nt<EPI_RKV><<<gDD, T>>>(apre, sa_o_w, sa_o_b, v, r, rkv,
                                 N_, D_, D_, 0, 0, 0, 0.f);
    // x_mid = x + rkv @ tm_out_w^T
    gemm_nt<EPI_ADD><<<gDD, T>>>(rkv, tm_out_w, nullptr, x, nullptr, xmid,
                                 N_, D_, D_, 0, 0, 0, 0.f);

    // ---- channel-mix branch ----
    rmsnorm_kernel<<<N_, T>>>(xmid, norm2_w, x2);
    mix2_kernel<<<N_, T>>>(x2, cm_mix_k, cm_mix_r, xa, xb);

    dim3 gDI(DI_ / BN, N_ / BM, 1);             // (32, 64)
    gemm_nt<EPI_RELU2><<<gDI, T>>>(xa, cm_key_w, nullptr, nullptr, nullptr, kcm,
                                   N_, DI_, D_, 0, 0, 0, 0.f);
    gemm_nt<EPI_NONE><<<gDD, T>>>(xb, cm_recept_w, nullptr, nullptr, nullptr, r2,
                                  N_, D_, D_, 0, 0, 0, 0.f);
    // out = x_mid + sigmoid(r2) * (kcm @ cm_value_w^T)
    gemm_nt<EPI_CMFIN><<<gDD, T>>>(kcm, cm_value_w, nullptr, xmid, r2, out,
                                   N_, D_, DI_, 0, 0, 0, 0.f);
}

// round 4
// speedup vs baseline: 1.7917x; 1.7909x over previous
#include <cuda_runtime.h>
#include <cuda_bf16.h>
#include <math.h>
#include <stdint.h>

#define D_    1024
#define A_    64
#define TOPK_ 32
#define B_    2
#define S_    4096
#define N_    (B_ * S_)
#define DI_   4096

typedef __nv_bfloat16 bf16;

// ---------------------------------------------------------------------------
// Device-global scratch (allocation-free rule)
// ---------------------------------------------------------------------------
__device__ __align__(256) float g_x1[N_ * D_];
__device__ __align__(256) float g_v[N_ * D_];
__device__ __align__(256) float g_r[N_ * D_];
__device__ __align__(256) float g_Vsa[N_ * D_];
__device__ __align__(256) float g_scores[(long long)B_ * S_ * S_];
__device__ __align__(256) float g_xmid[N_ * D_];
__device__ __align__(256) float g_x2[N_ * D_];
__device__ __align__(256) float g_r2[N_ * D_];
__device__ __align__(256) float g_qkb[128];

__device__ __align__(256) bf16 g_x1h[N_ * D_],  g_x1l[N_ * D_];
__device__ __align__(256) bf16 g_xah[N_ * D_],  g_xal[N_ * D_];
__device__ __align__(256) bf16 g_xbh[N_ * D_],  g_xbl[N_ * D_];
__device__ __align__(256) bf16 g_qkh[N_ * 128], g_qkl[N_ * 128];
__device__ __align__(256) bf16 g_aph[N_ * D_],  g_apl[N_ * D_];
__device__ __align__(256) bf16 g_rkh[N_ * D_],  g_rkl[N_ * D_];
__device__ __align__(256) bf16 g_kch[(long long)N_ * DI_], g_kcl[(long long)N_ * DI_];

__device__ __align__(256) bf16 g_wvh[D_ * D_],   g_wvl[D_ * D_];
__device__ __align__(256) bf16 g_wrh[D_ * D_],   g_wrl[D_ * D_];
__device__ __align__(256) bf16 g_wsvh[D_ * D_],  g_wsvl[D_ * D_];
__device__ __align__(256) bf16 g_woh[D_ * D_],   g_wol[D_ * D_];
__device__ __align__(256) bf16 g_wtoh[D_ * D_],  g_wtol[D_ * D_];
__device__ __align__(256) bf16 g_wcrh[D_ * D_],  g_wcrl[D_ * D_];
__device__ __align__(256) bf16 g_wckh[DI_ * D_], g_wckl[DI_ * D_];
__device__ __align__(256) bf16 g_wcvh[D_ * DI_], g_wcvl[D_ * DI_];
__device__ __align__(256) bf16 g_wqkh[128 * D_], g_wqkl[128 * D_];

// ---------------------------------------------------------------------------
// Helpers
// ---------------------------------------------------------------------------
__device__ __forceinline__ float sigmoidf_(float x) { return 1.f / (1.f + expf(-x)); }

__device__ __forceinline__ void splitstore(bf16* H, bf16* L, long long idx, float v)
{
    bf16 h = __float2bfloat16(v);
    H[idx] = h;
    L[idx] = __float2bfloat16(v - __bfloat162float(h));
}

__device__ __forceinline__ void store_planes4(bf16* H, bf16* L, long long idx, float4 v)
{
    splitstore(H, L, idx + 0, v.x); splitstore(H, L, idx + 1, v.y);
    splitstore(H, L, idx + 2, v.z); splitstore(H, L, idx + 3, v.w);
}

__device__ __forceinline__ uint32_t smem_u32(const void* p)
{
    uint32_t a;
    asm("{ .reg .u64 t; cvta.to.shared.u64 t, %1; cvt.u32.u64 %0, t; }" : "=r"(a) : "l"(p));
    return a;
}
__device__ __forceinline__ void cp16(uint32_t s, const void* g)
{
    asm volatile("cp.async.cg.shared.global [%0], [%1], 16;" :: "r"(s), "l"(g));
}
__device__ __forceinline__ void ldsm4(uint32_t* r, uint32_t addr)
{
    asm volatile("ldmatrix.sync.aligned.m8n8.x4.shared.b16 {%0,%1,%2,%3}, [%4];"
                 : "=r"(r[0]), "=r"(r[1]), "=r"(r[2]), "=r"(r[3]) : "r"(addr));
}
__device__ __forceinline__ void mma16816(float* c, const uint32_t* a,
                                         uint32_t b0, uint32_t b1)
{
    asm volatile(
        "mma.sync.aligned.m16n8k16.row.col.f32.bf16.bf16.f32 "
        "{%0,%1,%2,%3},{%4,%5,%6,%7},{%8,%9},{%0,%1,%2,%3};"
        : "+f"(c[0]), "+f"(c[1]), "+f"(c[2]), "+f"(c[3])
        : "r"(a[0]), "r"(a[1]), "r"(a[2]), "r"(a[3]), "r"(b0), "r"(b1));
}

#define EF32    0
#define EPLB    1   /* planes, +bias                     */
#define ERELU2  2   /* planes, relu(acc)^2               */
#define ERKV    3   /* planes, sigmoid(E1)*(acc+bias+E0) */
#define EADD    4   /* f32, acc+E0                       */
#define ECMFIN  5   /* f32, E0 + sigmoid(E1)*acc         */

// ---------------------------------------------------------------------------
// bf16 split-precision NT GEMM on mma.sync (HMMA):
//   C[row,col] = sum_k A[row,k]*B[col,k], computed as Ah*Bh + Al*Bh + Ah*Bl
// CTA tile 128x128, BK=32, 3-stage cp.async, 8 warps (2m x 4n), warp 64x32.
// smem rows padded to 80B -> conflict-free ldmatrix without swizzle.
// ---------------------------------------------------------------------------
#define ROWB   80
#define PLANE  (128 * ROWB)        /* 10240 B */
#define STAGEB (4 * PLANE)         /* 40960 B */
#define NSTAGE 3

template<int EPI>
__global__ __launch_bounds__(256, 1)
void gemm_mma(const bf16* __restrict__ Ah, const bf16* __restrict__ Al, int lda,
              const bf16* __restrict__ Bh, const bf16* __restrict__ Bl, int ldb,
              const float* __restrict__ bias, const float* __restrict__ E0,
              const float* __restrict__ E1,
              float* __restrict__ Cf, bf16* __restrict__ Ch, bf16* __restrict__ Cl,
              int ldc, int K, float scale,
              long long sA, long long sB, long long sC)
{
    extern __shared__ __align__(256) char smem[];

    Ah += (long long)blockIdx.z * sA;  Al += (long long)blockIdx.z * sA;
    Bh += (long long)blockIdx.z * sB;  Bl += (long long)blockIdx.z * sB;
    const long long zC = (long long)blockIdx.z * sC;

    const int tid  = threadIdx.x;
    const int lane = tid & 31;
    const int wid  = tid >> 5;
    const int wm   = wid & 1;        // 2 warp rows (64 each)
    const int wn   = wid >> 1;       // 4 warp cols (32 each)
    const int row0 = blockIdx.y * 128;
    const int col0 = blockIdx.x * 128;

    const uint32_t sbase = smem_u32(smem);
    const int NC = K >> 5;

    float acc[4][4][4];
    #pragma unroll
    for (int mf = 0; mf < 4; mf++)
        #pragma unroll
        for (int nf = 0; nf < 4; nf++)
            #pragma unroll
            for (int e = 0; e < 4; e++) acc[mf][nf][e] = 0.f;

    auto load_stage = [&](int c, int s) {
        uint32_t st = sbase + s * STAGEB;
        int k0 = c << 5;
        const bf16* srcs[4] = { Ah, Al, Bh, Bl };
        #pragma unroll
        for (int p = 0; p < 4; p++) {
            int base = (p < 2) ? row0 : col0;
            int ld   = (p < 2) ? lda : ldb;
            const bf16* sp = srcs[p] + (long long)base * ld + k0;
            uint32_t db = st + p * PLANE;
            #pragma unroll
            for (int i = tid; i < 512; i += 256) {
                int rr = i >> 2, ch = i & 3;
                cp16(db + rr * ROWB + ch * 16, sp + (long long)rr * ld + ch * 8);
            }
        }
        asm volatile("cp.async.commit_group;" ::: "memory");
    };

    load_stage(0, 0);
    if (NC > 1) load_stage(1, 1);

    for (int c = 0; c < NC; c++) {
        int s = c % NSTAGE;
        if (c + 1 < NC) asm volatile("cp.async.wait_group 1;" ::: "memory");
        else            asm volatile("cp.async.wait_group 0;" ::: "memory");
        __syncthreads();
        if (c + 2 < NC) load_stage(c + 2, (c + 2) % NSTAGE);

        uint32_t st = sbase + s * STAGEB;
        #pragma unroll
        for (int kk = 0; kk < 2; kk++) {
            uint32_t aH[4][4], aL[4][4], bH[2][4], bL[2][4];
            int chunk = (kk * 2 + (lane >> 4)) * 16;
            int arow  = wm * 64 + (lane & 15);
            #pragma unroll
            for (int mf = 0; mf < 4; mf++) {
                uint32_t off = (uint32_t)(arow + mf * 16) * ROWB + chunk;
                ldsm4(aH[mf], st + off);
                ldsm4(aL[mf], st + PLANE + off);
            }
            int brow = wn * 32 + (lane & 7) + ((lane >> 3) & 1) * 8;
            #pragma unroll
            for (int np = 0; np < 2; np++) {
                uint32_t off = (uint32_t)(brow + np * 16) * ROWB + chunk;
                ldsm4(bH[np], st + 2 * PLANE + off);
                ldsm4(bL[np], st + 3 * PLANE + off);
            }
            #pragma unroll
            for (int mf = 0; mf < 4; mf++)
                #pragma unroll
                for (int nf = 0; nf < 4; nf++) {
                    int np = nf >> 1, sl = nf & 1;
                    mma16816(acc[mf][nf], aH[mf], bH[np][sl], bH[np][2 + sl]);
                }
            #pragma unroll
            for (int mf = 0; mf < 4; mf++)
                #pragma unroll
                for (int nf = 0; nf < 4; nf++) {
                    int np = nf >> 1, sl = nf & 1;
                    mma16816(acc[mf][nf], aL[mf], bH[np][sl], bH[np][2 + sl]);
                }
            #pragma unroll
            for (int mf = 0; mf < 4; mf++)
                #pragma unroll
                for (int nf = 0; nf < 4; nf++) {
                    int np = nf >> 1, sl = nf & 1;
                    mma16816(acc[mf][nf], aH[mf], bL[np][sl], bL[np][2 + sl]);
                }
        }
    }

    // ---- epilogue: registers -> global, fused ops ----
    #pragma unroll
    for (int mf = 0; mf < 4; mf++) {
        #pragma unroll
        for (int nf = 0; nf < 4; nf++) {
            int rA = row0 + wm * 64 + mf * 16 + (lane >> 2);
            int cB = col0 + wn * 32 + nf * 8 + (lane & 3) * 2;
            #pragma unroll
            for (int h = 0; h < 2; h++) {
                int rr = rA + h * 8;
                long long idx = (long long)rr * ldc + cB + zC;
                float v0 = acc[mf][nf][h * 2 + 0];
                float v1 = acc[mf][nf][h * 2 + 1];
                if (EPI == EF32) {
                    float o0 = v0 * scale, o1 = v1 * scale;
                    if (bias) { o0 += bias[cB]; o1 += bias[cB + 1]; }
                    *(float2*)(Cf + idx) = make_float2(o0, o1);
                } else if (EPI == EPLB) {
                    splitstore(Ch, Cl, idx,     v0 + bias[cB]);
                    splitstore(Ch, Cl, idx + 1, v1 + bias[cB + 1]);
                } else if (EPI == ERELU2) {
                    float u0 = fmaxf(v0, 0.f), u1 = fmaxf(v1, 0.f);
                    splitstore(Ch, Cl, idx,     u0 * u0);
                    splitstore(Ch, Cl, idx + 1, u1 * u1);
                } else if (EPI == ERKV) {
                    splitstore(Ch, Cl, idx,
                               sigmoidf_(E1[idx]) * (v0 + bias[cB] + E0[idx]));
                    splitstore(Ch, Cl, idx + 1,
                               sigmoidf_(E1[idx + 1]) * (v1 + bias[cB + 1] + E0[idx + 1]));
                } else if (EPI == EADD) {
                    *(float2*)(Cf + idx) = make_float2(v0 + E0[idx], v1 + E0[idx + 1]);
                } else { // ECMFIN
                    float o0 = E0[idx]     + sigmoidf_(E1[idx])     * v0;
                    float o1 = E0[idx + 1] + sigmoidf_(E1[idx + 1]) * v1;
                    *(float2*)(Cf + idx) = make_float2(o0, o1);
                }
            }
        }
    }
}

// ---------------------------------------------------------------------------
// Elementwise kernels
// ---------------------------------------------------------------------------
__global__ __launch_bounds__(256)
void splitw_kernel(const float* __restrict__ w, bf16* __restrict__ h,
                   bf16* __restrict__ l, int n4)
{
    for (int i = blockIdx.x * 256 + threadIdx.x; i < n4; i += gridDim.x * 256) {
        float4 v = ((const float4*)w)[i];
        store_planes4(h, l, (long long)i * 4, v);
    }
}

__global__ __launch_bounds__(256)
void packqk_kernel(const float* __restrict__ qw, const float* __restrict__ kw,
                   bf16* __restrict__ h, bf16* __restrict__ l)
{
    int i = blockIdx.x * 256 + threadIdx.x;           // 128*256 float4s
    if (i < 128 * 256) {
        int row = i >> 8, c4 = i & 255;
        float4 v = (row < 64) ? ((const float4*)qw)[row * 256 + c4]
                              : ((const float4*)kw)[(row - 64) * 256 + c4];
        store_planes4(h, l, (long long)i * 4, v);
    }
}

__global__ void packqkb_kernel(const float* __restrict__ qb, const float* __restrict__ kb,
                               float* __restrict__ o)
{
    int t = threadIdx.x;
    if (t < 128) o[t] = (t < 64) ? qb[t] : kb[t - 64];
}

__global__ __launch_bounds__(256)
void rmsnorm_kernel(const float* __restrict__ x, const float* __restrict__ w,
                    float* __restrict__ outf, bf16* __restrict__ oh, bf16* __restrict__ ol)
{
    int n = blockIdx.x, tid = threadIdx.x;
    float4 xv = ((const float4*)(x + (long)n * D_))[tid];
    float ss = xv.x*xv.x + xv.y*xv.y + xv.z*xv.z + xv.w*xv.w;
    #pragma unroll
    for (int off = 16; off; off >>= 1) ss += __shfl_xor_sync(~0u, ss, off);
    __shared__ float wss[8];  __shared__ float s_scale;
    if ((tid & 31) == 0) wss[tid >> 5] = ss;
    __syncthreads();
    if (tid == 0) {
        float tot = 0.f;
        #pragma unroll
        for (int i = 0; i < 8; i++) tot += wss[i];
        s_scale = 1.f / (sqrtf(tot / (float)D_) + 1e-8f);
    }
    __syncthreads();
    float sc = s_scale;
    float4 wv = ((const float4*)w)[tid];
    float4 ov = make_float4(xv.x*wv.x*sc, xv.y*wv.y*sc, xv.z*wv.z*sc, xv.w*wv.w*sc);
    long long idx = (long long)n * D_ + tid * 4;
    ((float4*)(outf))[idx >> 2] = ov;
    if (oh) store_planes4(oh, ol, idx, ov);
}

__global__ __launch_bounds__(256)
void mix2_kernel(const float* __restrict__ x,
                 const float* __restrict__ mA, const float* __restrict__ mB,
                 bf16* __restrict__ ah, bf16* __restrict__ al,
                 bf16* __restrict__ bh, bf16* __restrict__ bl)
{
    int n = blockIdx.x, tid = threadIdx.x;
    int prev = ((n & (S_ - 1)) == 0) ? n : n - 1;
    float4 cur = ((const float4*)(x + (long)n    * D_))[tid];
    float4 pv  = ((const float4*)(x + (long)prev * D_))[tid];
    float4 ma  = ((const float4*)mA)[tid];
    float4 mb  = ((const float4*)mB)[tid];
    long long idx = (long long)n * D_ + tid * 4;
    float4 oa = make_float4(cur.x*ma.x + pv.x*(1.f-ma.x), cur.y*ma.y + pv.y*(1.f-ma.y),
                            cur.z*ma.z + pv.z*(1.f-ma.z), cur.w*ma.w + pv.w*(1.f-ma.w));
    float4 ob = make_float4(cur.x*mb.x + pv.x*(1.f-mb.x), cur.y*mb.y + pv.y*(1.f-mb.y),
                            cur.z*mb.z + pv.z*(1.f-mb.z), cur.w*mb.w + pv.w*(1.f-mb.w));
    store_planes4(ah, al, idx, oa);
    store_planes4(bh, bl, idx, ob);
}

// ---------------------------------------------------------------------------
// Top-k(32) + softmax + sparse V gather -> bf16 planes
// ---------------------------------------------------------------------------
__global__ __launch_bounds__(256)
void topk_attn_kernel(const float* __restrict__ scores, const float* __restrict__ V,
                      bf16* __restrict__ oh, bf16* __restrict__ ol)
{
    int q = blockIdx.x, b = q >> 12, qs = q & (S_ - 1), tid = threadIdx.x;
    const float* srow = scores + (long long)b * S_ * S_ + (long long)qs * S_;
    float s[16];
    #pragma unroll
    for (int i = 0; i < 16; i++) s[i] = srow[i * 256 + tid];

    __shared__ float wv[8]; __shared__ int wi[8];
    __shared__ float top_val[TOPK_]; __shared__ int top_idx[TOPK_];
    __shared__ int s_win;
    const float NEG = -__int_as_float(0x7f800000);

    for (int t = 0; t < TOPK_; t++) {
        float best = NEG; int bi = 0;
        #pragma unroll
        for (int i = 0; i < 16; i++) if (s[i] > best) { best = s[i]; bi = i; }
        int gidx = bi * 256 + tid;
        #pragma unroll
        for (int off = 16; off; off >>= 1) {
            float ov = __shfl_down_sync(~0u, best, off);
            int   oi = __shfl_down_sync(~0u, gidx, off);
            if (ov > best) { best = ov; gidx = oi; }
        }
        if ((tid & 31) == 0) { wv[tid >> 5] = best; wi[tid >> 5] = gidx; }
        __syncthreads();
        if (tid == 0) {
            float bb = wv[0]; int bbi = wi[0];
            #pragma unroll
            for (int w = 1; w < 8; w++) if (wv[w] > bb) { bb = wv[w]; bbi = wi[w]; }
            top_val[t] = bb; top_idx[t] = bbi; s_win = bbi;
        }
        __syncthreads();
        int win = s_win;
        if ((win & 255) == tid) s[win >> 8] = NEG;
    }

    __shared__ float wts[TOPK_];
    if (tid < 32) {
        float e = expf(top_val[tid] - top_val[0]);
        float ssum = e;
        #pragma unroll
        for (int off = 16; off; off >>= 1) ssum += __shfl_xor_sync(~0u, ssum, off);
        wts[tid] = e / ssum;
    }
    __syncthreads();

    const float* Vb = V + (long long)b * S_ * D_;
    float4 acc = make_float4(0.f, 0.f, 0.f, 0.f);
    #pragma unroll
    for (int t = 0; t < TOPK_; t++) {
        float w = wts[t];
        float4 vr = *(const float4*)&Vb[(long long)top_idx[t] * D_ + tid * 4];
        acc.x += w*vr.x; acc.y += w*vr.y; acc.z += w*vr.z; acc.w += w*vr.w;
    }
    store_planes4(oh, ol, (long long)q * D_ + tid * 4, acc);
}

// ---------------------------------------------------------------------------
// Host
// ---------------------------------------------------------------------------
template <typename T> static void* symaddr(T& sym)
{ void* p = nullptr; cudaGetSymbolAddress(&p, sym); return p; }

extern "C" void kernel_launch(void* const* d_in, const int* in_sizes, int n_in,
                              void* d_out, int out_size)
{
    const float* x        = (const float*)d_in[0];
    const float* norm1_w  = (const float*)d_in[1];
    const float* tm_mix_v = (const float*)d_in[3];
    const float* tm_mix_r = (const float*)d_in[4];
    const float* tm_value_w  = (const float*)d_in[6];
    const float* tm_recept_w = (const float*)d_in[7];
    const float* tm_out_w = (const float*)d_in[8];
    const float* sa_q_w   = (const float*)d_in[9];
    const float* sa_q_b   = (const float*)d_in[10];
    const float* sa_k_w   = (const float*)d_in[11];
    const float* sa_k_b   = (const float*)d_in[12];
    const float* sa_v_w   = (const float*)d_in[13];
    const float* sa_v_b   = (const float*)d_in[14];
    const float* sa_o_w   = (const float*)d_in[15];
    const float* sa_o_b   = (const float*)d_in[16];
    const float* norm2_w  = (const float*)d_in[17];
    const float* cm_mix_k = (const float*)d_in[18];
    const float* cm_mix_r = (const float*)d_in[19];
    const float* cm_key_w = (const float*)d_in[20];
    const float* cm_recept_w = (const float*)d_in[21];
    const float* cm_value_w  = (const float*)d_in[22];
    float* out = (float*)d_out;

    float* x1  = (float*)symaddr(g_x1);   float* v   = (float*)symaddr(g_v);
    float* r   = (float*)symaddr(g_r);    float* Vsa = (float*)symaddr(g_Vsa);
    float* sc  = (float*)symaddr(g_scores);
    float* xmid= (float*)symaddr(g_xmid); float* x2  = (float*)symaddr(g_x2);
    float* r2  = (float*)symaddr(g_r2);   float* qkb = (float*)symaddr(g_qkb);

    bf16 *x1h=(bf16*)symaddr(g_x1h), *x1l=(bf16*)symaddr(g_x1l);
    bf16 *xah=(bf16*)symaddr(g_xah), *xal=(bf16*)symaddr(g_xal);
    bf16 *xbh=(bf16*)symaddr(g_xbh), *xbl=(bf16*)symaddr(g_xbl);
    bf16 *qkh=(bf16*)symaddr(g_qkh), *qkl=(bf16*)symaddr(g_qkl);
    bf16 *aph=(bf16*)symaddr(g_aph), *apl=(bf16*)symaddr(g_apl);
    bf16 *rkh=(bf16*)symaddr(g_rkh), *rkl=(bf16*)symaddr(g_rkl);
    bf16 *kch=(bf16*)symaddr(g_kch), *kcl=(bf16*)symaddr(g_kcl);
    bf16 *wvh=(bf16*)symaddr(g_wvh), *wvl=(bf16*)symaddr(g_wvl);
    bf16 *wrh=(bf16*)symaddr(g_wrh), *wrl=(bf16*)symaddr(g_wrl);
    bf16 *wsvh=(bf16*)symaddr(g_wsvh), *wsvl=(bf16*)symaddr(g_wsvl);
    bf16 *woh=(bf16*)symaddr(g_woh), *wol=(bf16*)symaddr(g_wol);
    bf16 *wtoh=(bf16*)symaddr(g_wtoh), *wtol=(bf16*)symaddr(g_wtol);
    bf16 *wcrh=(bf16*)symaddr(g_wcrh), *wcrl=(bf16*)symaddr(g_wcrl);
    bf16 *wckh=(bf16*)symaddr(g_wckh), *wckl=(bf16*)symaddr(g_wckl);
    bf16 *wcvh=(bf16*)symaddr(g_wcvh), *wcvl=(bf16*)symaddr(g_wcvl);
    bf16 *wqkh=(bf16*)symaddr(g_wqkh), *wqkl=(bf16*)symaddr(g_wqkl);

    const int SMB = NSTAGE * STAGEB;   // 122880
    cudaFuncSetAttribute(gemm_mma<EF32>,   cudaFuncAttributeMaxDynamicSharedMemorySize, SMB);
    cudaFuncSetAttribute(gemm_mma<EPLB>,   cudaFuncAttributeMaxDynamicSharedMemorySize, SMB);
    cudaFuncSetAttribute(gemm_mma<ERELU2>, cudaFuncAttributeMaxDynamicSharedMemorySize, SMB);
    cudaFuncSetAttribute(gemm_mma<ERKV>,   cudaFuncAttributeMaxDynamicSharedMemorySize, SMB);
    cudaFuncSetAttribute(gemm_mma<EADD>,   cudaFuncAttributeMaxDynamicSharedMemorySize, SMB);
    cudaFuncSetAttribute(gemm_mma<ECMFIN>, cudaFuncAttributeMaxDynamicSharedMemorySize, SMB);

    // ---- weight split ----
    splitw_kernel<<<512, 256>>>(tm_value_w,  wvh, wvl,  D_*D_/4);
    splitw_kernel<<<512, 256>>>(tm_recept_w, wrh, wrl,  D_*D_/4);
    splitw_kernel<<<512, 256>>>(sa_v_w,      wsvh,wsvl, D_*D_/4);
    splitw_kernel<<<512, 256>>>(sa_o_w,      woh, wol,  D_*D_/4);
    splitw_kernel<<<512, 256>>>(tm_out_w,    wtoh,wtol, D_*D_/4);
    splitw_kernel<<<512, 256>>>(cm_recept_w, wcrh,wcrl, D_*D_/4);
    splitw_kernel<<<2048,256>>>(cm_key_w,    wckh,wckl, DI_*D_/4);
    splitw_kernel<<<2048,256>>>(cm_value_w,  wcvh,wcvl, D_*DI_/4);
    packqk_kernel<<<128, 256>>>(sa_q_w, sa_k_w, wqkh, wqkl);
    packqkb_kernel<<<1, 128>>>(sa_q_b, sa_k_b, qkb);

    // ---- time-mix ----
    rmsnorm_kernel<<<N_, 256>>>(x, norm1_w, x1, x1h, x1l);
    mix2_kernel<<<N_, 256>>>(x1, tm_mix_v, tm_mix_r, xah, xal, xbh, xbl);

    dim3 gDD(8, 64, 1);
    gemm_mma<EF32><<<gDD, 256, SMB>>>(xah, xal, D_, wvh, wvl, D_,
        nullptr, nullptr, nullptr, v, nullptr, nullptr, D_, D_, 1.f, 0, 0, 0);
    gemm_mma<EF32><<<gDD, 256, SMB>>>(xbh, xbl, D_, wrh, wrl, D_,
        nullptr, nullptr, nullptr, r, nullptr, nullptr, D_, D_, 1.f, 0, 0, 0);
    gemm_mma<EPLB><<<dim3(1,64,1), 256, SMB>>>(x1h, x1l, D_, wqkh, wqkl, D_,
        qkb, nullptr, nullptr, nullptr, qkh, qkl, 128, D_, 1.f, 0, 0, 0);
    gemm_mma<EF32><<<gDD, 256, SMB>>>(x1h, x1l, D_, wsvh, wsvl, D_,
        sa_v_b, nullptr, nullptr, Vsa, nullptr, nullptr, D_, D_, 1.f, 0, 0, 0);

    // scores[b] = Q @ K^T / 8
    gemm_mma<EF32><<<dim3(32,32,2), 256, SMB>>>(qkh, qkl, 128, qkh + 64, qkl + 64, 128,
        nullptr, nullptr, nullptr, sc, nullptr, nullptr, S_, 64, 0.125f,
        (long long)S_*128, (long long)S_*128, (long long)S_*S_);

    topk_attn_kernel<<<N_, 256>>>(sc, Vsa, aph, apl);

    gemm_mma<ERKV><<<gDD, 256, SMB>>>(aph, apl, D_, woh, wol, D_,
        sa_o_b, v, r, nullptr, rkh, rkl, D_, D_, 1.f, 0, 0, 0);
    gemm_mma<EADD><<<gDD, 256, SMB>>>(rkh, rkl, D_, wtoh, wtol, D_,
        nullptr, x, nullptr, xmid, nullptr, nullptr, D_, D_, 1.f, 0, 0, 0);

    // ---- channel-mix ----
    rmsnorm_kernel<<<N_, 256>>>(xmid, norm2_w, x2, nullptr, nullptr);
    mix2_kernel<<<N_, 256>>>(x2, cm_mix_k, cm_mix_r, xah, xal, xbh, xbl);

    gemm_mma<ERELU2><<<dim3(32,64,1), 256, SMB>>>(xah, xal, D_, wckh, wckl, D_,
        nullptr, nullptr, nullptr, nullptr, kch, kcl, DI_, D_, 1.f, 0, 0, 0);
    gemm_mma<EF32><<<gDD, 256, SMB>>>(xbh, xbl, D_, wcrh, wcrl, D_,
        nullptr, nullptr, nullptr, r2, nullptr, nullptr, D_, D_, 1.f, 0, 0, 0);
    gemm_mma<ECMFIN><<<gDD, 256, SMB>>>(kch, kcl, DI_, wcvh, wcvl, DI_,
        nullptr, xmid, r2, out, nullptr, nullptr, D_, DI_, 1.f, 0, 0, 0);
}

// round 5
// speedup vs baseline: 2.1886x; 1.2216x over previous
#include <cuda_runtime.h>
#include <cuda_bf16.h>
#include <math.h>
#include <stdint.h>

#define D_    1024
#define A_    64
#define TOPK_ 32
#define B_    2
#define S_    4096
#define N_    (B_ * S_)
#define DI_   4096

typedef __nv_bfloat16 bf16;

// ---------------------------------------------------------------------------
// Device-global scratch (allocation-free rule)
// ---------------------------------------------------------------------------
__device__ __align__(256) float g_x1[N_ * D_];
__device__ __align__(256) float g_v[N_ * D_];
__device__ __align__(256) float g_r[N_ * D_];
__device__ __align__(256) float g_Vsa[N_ * D_];
__device__ __align__(256) float g_scores[(long long)B_ * S_ * S_];
__device__ __align__(256) float g_xmid[N_ * D_];
__device__ __align__(256) float g_x2[N_ * D_];
__device__ __align__(256) float g_r2[N_ * D_];
__device__ __align__(256) float g_qkb[128];

__device__ __align__(256) bf16 g_x1h[N_ * D_],  g_x1l[N_ * D_];
__device__ __align__(256) bf16 g_xah[N_ * D_],  g_xal[N_ * D_];
__device__ __align__(256) bf16 g_xbh[N_ * D_],  g_xbl[N_ * D_];
__device__ __align__(256) bf16 g_qkh[N_ * 128], g_qkl[N_ * 128];
__device__ __align__(256) bf16 g_aph[N_ * D_],  g_apl[N_ * D_];
__device__ __align__(256) bf16 g_rkh[N_ * D_],  g_rkl[N_ * D_];
__device__ __align__(256) bf16 g_kch[(long long)N_ * DI_], g_kcl[(long long)N_ * DI_];

__device__ __align__(256) bf16 g_wvh[D_ * D_],   g_wvl[D_ * D_];
__device__ __align__(256) bf16 g_wrh[D_ * D_],   g_wrl[D_ * D_];
__device__ __align__(256) bf16 g_wsvh[D_ * D_],  g_wsvl[D_ * D_];
__device__ __align__(256) bf16 g_woh[D_ * D_],   g_wol[D_ * D_];
__device__ __align__(256) bf16 g_wtoh[D_ * D_],  g_wtol[D_ * D_];
__device__ __align__(256) bf16 g_wcrh[D_ * D_],  g_wcrl[D_ * D_];
__device__ __align__(256) bf16 g_wckh[DI_ * D_], g_wckl[DI_ * D_];
__device__ __align__(256) bf16 g_wcvh[D_ * DI_], g_wcvl[D_ * DI_];
__device__ __align__(256) bf16 g_wqkh[128 * D_], g_wqkl[128 * D_];

// ---------------------------------------------------------------------------
// Helpers
// ---------------------------------------------------------------------------
__device__ __forceinline__ float sigmoidf_(float x) { return 1.f / (1.f + expf(-x)); }

__device__ __forceinline__ void splitstore(bf16* H, bf16* L, long long idx, float v)
{
    bf16 h = __float2bfloat16(v);
    H[idx] = h;
    L[idx] = __float2bfloat16(v - __bfloat162float(h));
}

__device__ __forceinline__ void store_planes4(bf16* H, bf16* L, long long idx, float4 v)
{
    splitstore(H, L, idx + 0, v.x); splitstore(H, L, idx + 1, v.y);
    splitstore(H, L, idx + 2, v.z); splitstore(H, L, idx + 3, v.w);
}

__device__ __forceinline__ uint32_t smem_u32(const void* p)
{
    uint32_t a;
    asm("{ .reg .u64 t; cvta.to.shared.u64 t, %1; cvt.u32.u64 %0, t; }" : "=r"(a) : "l"(p));
    return a;
}
__device__ __forceinline__ void cp16(uint32_t s, const void* g)
{
    asm volatile("cp.async.cg.shared.global [%0], [%1], 16;" :: "r"(s), "l"(g));
}
__device__ __forceinline__ void ldsm4(uint32_t* r, uint32_t addr)
{
    asm volatile("ldmatrix.sync.aligned.m8n8.x4.shared.b16 {%0,%1,%2,%3}, [%4];"
                 : "=r"(r[0]), "=r"(r[1]), "=r"(r[2]), "=r"(r[3]) : "r"(addr));
}
__device__ __forceinline__ void mma16816(float* c, const uint32_t* a,
                                         uint32_t b0, uint32_t b1)
{
    asm volatile(
        "mma.sync.aligned.m16n8k16.row.col.f32.bf16.bf16.f32 "
        "{%0,%1,%2,%3},{%4,%5,%6,%7},{%8,%9},{%0,%1,%2,%3};"
        : "+f"(c[0]), "+f"(c[1]), "+f"(c[2]), "+f"(c[3])
        : "r"(a[0]), "r"(a[1]), "r"(a[2]), "r"(a[3]), "r"(b0), "r"(b1));
}

#define EF32    0
#define EPLB    1   /* planes, +bias                     */
#define ERELU2  2   /* planes, relu(acc)^2               */
#define ERKV    3   /* planes, sigmoid(E1)*(acc+bias+E0) */
#define EADD    4   /* f32, acc+E0                       */
#define ECMFIN  5   /* f32, E0 + sigmoid(E1)*acc         */

// ---------------------------------------------------------------------------
// bf16 split-precision NT GEMM on mma.sync (HMMA):
//   C = Ah*Bh + Al*Bh + Ah*Bl, fp32 accum.
// CTA 128x128, BK=32, 2-stage cp.async (80KB smem -> 2 CTAs/SM),
// 8 warps (2m x 4n), warp tile 64x32. 80B-padded rows, conflict-free ldmatrix.
// ---------------------------------------------------------------------------
#define ROWB   80
#define PLANE  (128 * ROWB)        /* 10240 B */
#define STAGEB (4 * PLANE)         /* 40960 B */
#define NSTAGE 2

template<int EPI>
__global__ __launch_bounds__(256, 2)
void gemm_mma(const bf16* __restrict__ Ah, const bf16* __restrict__ Al, int lda,
              const bf16* __restrict__ Bh, const bf16* __restrict__ Bl, int ldb,
              const float* __restrict__ bias, const float* __restrict__ E0,
              const float* __restrict__ E1,
              float* __restrict__ Cf, bf16* __restrict__ Ch, bf16* __restrict__ Cl,
              int ldc, int K, float scale,
              long long sA, long long sB, long long sC)
{
    extern __shared__ __align__(256) char smem[];

    Ah += (long long)blockIdx.z * sA;  Al += (long long)blockIdx.z * sA;
    Bh += (long long)blockIdx.z * sB;  Bl += (long long)blockIdx.z * sB;
    const long long zC = (long long)blockIdx.z * sC;

    const int tid  = threadIdx.x;
    const int lane = tid & 31;
    const int wid  = tid >> 5;
    const int wm   = wid & 1;
    const int wn   = wid >> 1;
    const int row0 = blockIdx.y * 128;
    const int col0 = blockIdx.x * 128;

    const uint32_t sbase = smem_u32(smem);
    const int NC = K >> 5;

    float acc[4][4][4];
    #pragma unroll
    for (int mf = 0; mf < 4; mf++)
        #pragma unroll
        for (int nf = 0; nf < 4; nf++)
            #pragma unroll
            for (int e = 0; e < 4; e++) acc[mf][nf][e] = 0.f;

    auto load_stage = [&](int c, int s) {
        uint32_t st = sbase + s * STAGEB;
        int k0 = c << 5;
        const bf16* srcs[4] = { Ah, Al, Bh, Bl };
        #pragma unroll
        for (int p = 0; p < 4; p++) {
            int base = (p < 2) ? row0 : col0;
            int ld   = (p < 2) ? lda : ldb;
            const bf16* sp = srcs[p] + (long long)base * ld + k0;
            uint32_t db = st + p * PLANE;
            #pragma unroll
            for (int i = tid; i < 512; i += 256) {
                int rr = i >> 2, ch = i & 3;
                cp16(db + rr * ROWB + ch * 16, sp + (long long)rr * ld + ch * 8);
            }
        }
        asm volatile("cp.async.commit_group;" ::: "memory");
    };

    auto load_frags = [&](uint32_t st, int kk,
                          uint32_t (&aH)[4][4], uint32_t (&aL)[4][4],
                          uint32_t (&bH)[2][4], uint32_t (&bL)[2][4]) {
        int chunk = (kk * 2 + (lane >> 4)) * 16;
        int arow  = wm * 64 + (lane & 15);
        #pragma unroll
        for (int mf = 0; mf < 4; mf++) {
            uint32_t off = (uint32_t)(arow + mf * 16) * ROWB + chunk;
            ldsm4(aH[mf], st + off);
            ldsm4(aL[mf], st + PLANE + off);
        }
        int brow = wn * 32 + (lane & 7) + ((lane >> 3) & 1) * 8;
        #pragma unroll
        for (int np = 0; np < 2; np++) {
            uint32_t off = (uint32_t)(brow + np * 16) * ROWB + chunk;
            ldsm4(bH[np], st + 2 * PLANE + off);
            ldsm4(bL[np], st + 3 * PLANE + off);
        }
    };

    auto do_mma = [&](uint32_t (&aH)[4][4], uint32_t (&aL)[4][4],
                      uint32_t (&bH)[2][4], uint32_t (&bL)[2][4]) {
        #pragma unroll
        for (int mf = 0; mf < 4; mf++)
            #pragma unroll
            for (int nf = 0; nf < 4; nf++) {
                int np = nf >> 1, sl = nf & 1;
                mma16816(acc[mf][nf], aH[mf], bH[np][sl], bH[np][2 + sl]);
            }
        #pragma unroll
        for (int mf = 0; mf < 4; mf++)
            #pragma unroll
            for (int nf = 0; nf < 4; nf++) {
                int np = nf >> 1, sl = nf & 1;
                mma16816(acc[mf][nf], aL[mf], bH[np][sl], bH[np][2 + sl]);
            }
        #pragma unroll
        for (int mf = 0; mf < 4; mf++)
            #pragma unroll
            for (int nf = 0; nf < 4; nf++) {
                int np = nf >> 1, sl = nf & 1;
                mma16816(acc[mf][nf], aH[mf], bL[np][sl], bL[np][2 + sl]);
            }
    };

    load_stage(0, 0);
    if (NC > 1) load_stage(1, 1);

    for (int c = 0; c < NC; c++) {
        int s = c & 1;
        if (c + 1 < NC) asm volatile("cp.async.wait_group 1;" ::: "memory");
        else            asm volatile("cp.async.wait_group 0;" ::: "memory");
        __syncthreads();
        uint32_t st = sbase + s * STAGEB;

        uint32_t aH[4][4], aL[4][4], bH[2][4], bL[2][4];
        load_frags(st, 0, aH, aL, bH, bL);
        do_mma(aH, aL, bH, bL);

        load_frags(st, 1, aH, aL, bH, bL);
        __syncthreads();                       // stage s fully consumed
        if (c + 2 < NC) load_stage(c + 2, s);  // safe to overwrite
        do_mma(aH, aL, bH, bL);
    }

    // ---- epilogue: registers -> global, fused ops ----
    #pragma unroll
    for (int mf = 0; mf < 4; mf++) {
        #pragma unroll
        for (int nf = 0; nf < 4; nf++) {
            int rA = row0 + wm * 64 + mf * 16 + (lane >> 2);
            int cB = col0 + wn * 32 + nf * 8 + (lane & 3) * 2;
            #pragma unroll
            for (int h = 0; h < 2; h++) {
                int rr = rA + h * 8;
                long long idx = (long long)rr * ldc + cB + zC;
                float v0 = acc[mf][nf][h * 2 + 0];
                float v1 = acc[mf][nf][h * 2 + 1];
                if (EPI == EF32) {
                    float o0 = v0 * scale, o1 = v1 * scale;
                    if (bias) { o0 += bias[cB]; o1 += bias[cB + 1]; }
                    *(float2*)(Cf + idx) = make_float2(o0, o1);
                } else if (EPI == EPLB) {
                    splitstore(Ch, Cl, idx,     v0 + bias[cB]);
                    splitstore(Ch, Cl, idx + 1, v1 + bias[cB + 1]);
                } else if (EPI == ERELU2) {
                    float u0 = fmaxf(v0, 0.f), u1 = fmaxf(v1, 0.f);
                    splitstore(Ch, Cl, idx,     u0 * u0);
                    splitstore(Ch, Cl, idx + 1, u1 * u1);
                } else if (EPI == ERKV) {
                    splitstore(Ch, Cl, idx,
                               sigmoidf_(E1[idx]) * (v0 + bias[cB] + E0[idx]));
                    splitstore(Ch, Cl, idx + 1,
                               sigmoidf_(E1[idx + 1]) * (v1 + bias[cB + 1] + E0[idx + 1]));
                } else if (EPI == EADD) {
                    *(float2*)(Cf + idx) = make_float2(v0 + E0[idx], v1 + E0[idx + 1]);
                } else { // ECMFIN
                    float o0 = E0[idx]     + sigmoidf_(E1[idx])     * v0;
                    float o1 = E0[idx + 1] + sigmoidf_(E1[idx + 1]) * v1;
                    *(float2*)(Cf + idx) = make_float2(o0, o1);
                }
            }
        }
    }
}

// ---------------------------------------------------------------------------
// Fused weight split: all 8 weight matrices + packed QK weight + QK bias
// in ONE launch (keeps GEMMs inside the ncu -s 5 window).
// Index space is float4 units.
// ---------------------------------------------------------------------------
#define R6   (6 * 262144)
#define RCK  (R6 + 1048576)
#define RCV  (RCK + 1048576)
#define RQK  (RCV + 32768)

__global__ __launch_bounds__(256)
void split_all_kernel(const float* w0, const float* w1, const float* w2,
                      const float* w3, const float* w4, const float* w5,
                      bf16* h0, bf16* l0, bf16* h1, bf16* l1, bf16* h2, bf16* l2,
                      bf16* h3, bf16* l3, bf16* h4, bf16* l4, bf16* h5, bf16* l5,
                      const float* ck, bf16* ckh, bf16* ckl,
                      const float* cv, bf16* cvh, bf16* cvl,
                      const float* qw, const float* kw, bf16* qkh, bf16* qkl,
                      const float* qb, const float* kb, float* qkbo)
{
    const float* ws[6] = { w0, w1, w2, w3, w4, w5 };
    bf16* hs[6] = { h0, h1, h2, h3, h4, h5 };
    bf16* ls[6] = { l0, l1, l2, l3, l4, l5 };

    if (blockIdx.x == 0 && threadIdx.x < 128)
        qkbo[threadIdx.x] = (threadIdx.x < 64) ? qb[threadIdx.x] : kb[threadIdx.x - 64];

    for (long long i = blockIdx.x * 256 + threadIdx.x; i < RQK;
         i += (long long)gridDim.x * 256) {
        if (i < R6) {
            int j = (int)(i >> 18);
            int off = (int)(i & 262143);
            store_planes4(hs[j], ls[j], (long long)off * 4, ((const float4*)ws[j])[off]);
        } else if (i < RCK) {
            long long off = i - R6;
            store_planes4(ckh, ckl, off * 4, ((const float4*)ck)[off]);
        } else if (i < RCV) {
            long long off = i - RCK;
            store_planes4(cvh, cvl, off * 4, ((const float4*)cv)[off]);
        } else {
            int off = (int)(i - RCV);
            int row = off >> 8, c4 = off & 255;
            float4 v = (row < 64) ? ((const float4*)qw)[row * 256 + c4]
                                  : ((const float4*)kw)[(row - 64) * 256 + c4];
            store_planes4(qkh, qkl, (long long)off * 4, v);
        }
    }
}

// ---------------------------------------------------------------------------
// RMSNorm / mix / topk (as R4)
// ---------------------------------------------------------------------------
__global__ __launch_bounds__(256)
void rmsnorm_kernel(const float* __restrict__ x, const float* __restrict__ w,
                    float* __restrict__ outf, bf16* __restrict__ oh, bf16* __restrict__ ol)
{
    int n = blockIdx.x, tid = threadIdx.x;
    float4 xv = ((const float4*)(x + (long)n * D_))[tid];
    float ss = xv.x*xv.x + xv.y*xv.y + xv.z*xv.z + xv.w*xv.w;
    #pragma unroll
    for (int off = 16; off; off >>= 1) ss += __shfl_xor_sync(~0u, ss, off);
    __shared__ float wss[8];  __shared__ float s_scale;
    if ((tid & 31) == 0) wss[tid >> 5] = ss;
    __syncthreads();
    if (tid == 0) {
        float tot = 0.f;
        #pragma unroll
        for (int i = 0; i < 8; i++) tot += wss[i];
        s_scale = 1.f / (sqrtf(tot / (float)D_) + 1e-8f);
    }
    __syncthreads();
    float sc = s_scale;
    float4 wv = ((const float4*)w)[tid];
    float4 ov = make_float4(xv.x*wv.x*sc, xv.y*wv.y*sc, xv.z*wv.z*sc, xv.w*wv.w*sc);
    long long idx = (long long)n * D_ + tid * 4;
    ((float4*)(outf))[idx >> 2] = ov;
    if (oh) store_planes4(oh, ol, idx, ov);
}

__global__ __launch_bounds__(256)
void mix2_kernel(const float* __restrict__ x,
                 const float* __restrict__ mA, const float* __restrict__ mB,
                 bf16* __restrict__ ah, bf16* __restrict__ al,
                 bf16* __restrict__ bh, bf16* __restrict__ bl)
{
    int n = blockIdx.x, tid = threadIdx.x;
    int prev = ((n & (S_ - 1)) == 0) ? n : n - 1;
    float4 cur = ((const float4*)(x + (long)n    * D_))[tid];
    float4 pv  = ((const float4*)(x + (long)prev * D_))[tid];
    float4 ma  = ((const float4*)mA)[tid];
    float4 mb  = ((const float4*)mB)[tid];
    long long idx = (long long)n * D_ + tid * 4;
    float4 oa = make_float4(cur.x*ma.x + pv.x*(1.f-ma.x), cur.y*ma.y + pv.y*(1.f-ma.y),
                            cur.z*ma.z + pv.z*(1.f-ma.z), cur.w*ma.w + pv.w*(1.f-ma.w));
    float4 ob = make_float4(cur.x*mb.x + pv.x*(1.f-mb.x), cur.y*mb.y + pv.y*(1.f-mb.y),
                            cur.z*mb.z + pv.z*(1.f-mb.z), cur.w*mb.w + pv.w*(1.f-mb.w));
    store_planes4(ah, al, idx, oa);
    store_planes4(bh, bl, idx, ob);
}

__global__ __launch_bounds__(256)
void topk_attn_kernel(const float* __restrict__ scores, const float* __restrict__ V,
                      bf16* __restrict__ oh, bf16* __restrict__ ol)
{
    int q = blockIdx.x, b = q >> 12, qs = q & (S_ - 1), tid = threadIdx.x;
    const float* srow = scores + (long long)b * S_ * S_ + (long long)qs * S_;
    float s[16];
    #pragma unroll
    for (int i = 0; i < 16; i++) s[i] = srow[i * 256 + tid];

    __shared__ float wv[8]; __shared__ int wi[8];
    __shared__ float top_val[TOPK_]; __shared__ int top_idx[TOPK_];
    __shared__ int s_win;
    const float NEG = -__int_as_float(0x7f800000);

    for (int t = 0; t < TOPK_; t++) {
        float best = NEG; int bi = 0;
        #pragma unroll
        for (int i = 0; i < 16; i++) if (s[i] > best) { best = s[i]; bi = i; }
        int gidx = bi * 256 + tid;
        #pragma unroll
        for (int off = 16; off; off >>= 1) {
            float ov = __shfl_down_sync(~0u, best, off);
            int   oi = __shfl_down_sync(~0u, gidx, off);
            if (ov > best) { best = ov; gidx = oi; }
        }
        if ((tid & 31) == 0) { wv[tid >> 5] = best; wi[tid >> 5] = gidx; }
        __syncthreads();
        if (tid == 0) {
            float bb = wv[0]; int bbi = wi[0];
            #pragma unroll
            for (int w = 1; w < 8; w++) if (wv[w] > bb) { bb = wv[w]; bbi = wi[w]; }
            top_val[t] = bb; top_idx[t] = bbi; s_win = bbi;
        }
        __syncthreads();
        int win = s_win;
        if ((win & 255) == tid) s[win >> 8] = NEG;
    }

    __shared__ float wts[TOPK_];
    if (tid < 32) {
        float e = expf(top_val[tid] - top_val[0]);
        float ssum = e;
        #pragma unroll
        for (int off = 16; off; off >>= 1) ssum += __shfl_xor_sync(~0u, ssum, off);
        wts[tid] = e / ssum;
    }
    __syncthreads();

    const float* Vb = V + (long long)b * S_ * D_;
    float4 acc = make_float4(0.f, 0.f, 0.f, 0.f);
    #pragma unroll
    for (int t = 0; t < TOPK_; t++) {
        float w = wts[t];
        float4 vr = *(const float4*)&Vb[(long long)top_idx[t] * D_ + tid * 4];
        acc.x += w*vr.x; acc.y += w*vr.y; acc.z += w*vr.z; acc.w += w*vr.w;
    }
    store_planes4(oh, ol, (long long)q * D_ + tid * 4, acc);
}

// ---------------------------------------------------------------------------
// Host
// ---------------------------------------------------------------------------
template <typename T> static void* symaddr(T& sym)
{ void* p = nullptr; cudaGetSymbolAddress(&p, sym); return p; }

extern "C" void kernel_launch(void* const* d_in, const int* in_sizes, int n_in,
                              void* d_out, int out_size)
{
    const float* x        = (const float*)d_in[0];
    const float* norm1_w  = (const float*)d_in[1];
    const float* tm_mix_v = (const float*)d_in[3];
    const float* tm_mix_r = (const float*)d_in[4];
    const float* tm_value_w  = (const float*)d_in[6];
    const float* tm_recept_w = (const float*)d_in[7];
    const float* tm_out_w = (const float*)d_in[8];
    const float* sa_q_w   = (const float*)d_in[9];
    const float* sa_q_b   = (const float*)d_in[10];
    const float* sa_k_w   = (const float*)d_in[11];
    const float* sa_k_b   = (const float*)d_in[12];
    const float* sa_v_w   = (const float*)d_in[13];
    const float* sa_v_b   = (const float*)d_in[14];
    const float* sa_o_w   = (const float*)d_in[15];
    const float* sa_o_b   = (const float*)d_in[16];
    const float* norm2_w  = (const float*)d_in[17];
    const float* cm_mix_k = (const float*)d_in[18];
    const float* cm_mix_r = (const float*)d_in[19];
    const float* cm_key_w = (const float*)d_in[20];
    const float* cm_recept_w = (const float*)d_in[21];
    const float* cm_value_w  = (const float*)d_in[22];
    float* out = (float*)d_out;

    float* x1  = (float*)symaddr(g_x1);   float* v   = (float*)symaddr(g_v);
    float* r   = (float*)symaddr(g_r);    float* Vsa = (float*)symaddr(g_Vsa);
    float* sc  = (float*)symaddr(g_scores);
    float* xmid= (float*)symaddr(g_xmid); float* x2  = (float*)symaddr(g_x2);
    float* r2  = (float*)symaddr(g_r2);   float* qkb = (float*)symaddr(g_qkb);

    bf16 *x1h=(bf16*)symaddr(g_x1h), *x1l=(bf16*)symaddr(g_x1l);
    bf16 *xah=(bf16*)symaddr(g_xah), *xal=(bf16*)symaddr(g_xal);
    bf16 *xbh=(bf16*)symaddr(g_xbh), *xbl=(bf16*)symaddr(g_xbl);
    bf16 *qkh=(bf16*)symaddr(g_qkh), *qkl=(bf16*)symaddr(g_qkl);
    bf16 *aph=(bf16*)symaddr(g_aph), *apl=(bf16*)symaddr(g_apl);
    bf16 *rkh=(bf16*)symaddr(g_rkh), *rkl=(bf16*)symaddr(g_rkl);
    bf16 *kch=(bf16*)symaddr(g_kch), *kcl=(bf16*)symaddr(g_kcl);
    bf16 *wvh=(bf16*)symaddr(g_wvh), *wvl=(bf16*)symaddr(g_wvl);
    bf16 *wrh=(bf16*)symaddr(g_wrh), *wrl=(bf16*)symaddr(g_wrl);
    bf16 *wsvh=(bf16*)symaddr(g_wsvh), *wsvl=(bf16*)symaddr(g_wsvl);
    bf16 *woh=(bf16*)symaddr(g_woh), *wol=(bf16*)symaddr(g_wol);
    bf16 *wtoh=(bf16*)symaddr(g_wtoh), *wtol=(bf16*)symaddr(g_wtol);
    bf16 *wcrh=(bf16*)symaddr(g_wcrh), *wcrl=(bf16*)symaddr(g_wcrl);
    bf16 *wckh=(bf16*)symaddr(g_wckh), *wckl=(bf16*)symaddr(g_wckl);
    bf16 *wcvh=(bf16*)symaddr(g_wcvh), *wcvl=(bf16*)symaddr(g_wcvl);
    bf16 *wqkh=(bf16*)symaddr(g_wqkh), *wqkl=(bf16*)symaddr(g_wqkl);

    const int SMB = NSTAGE * STAGEB;   // 81920 -> 2 CTAs/SM
    cudaFuncSetAttribute(gemm_mma<EF32>,   cudaFuncAttributeMaxDynamicSharedMemorySize, SMB);
    cudaFuncSetAttribute(gemm_mma<EPLB>,   cudaFuncAttributeMaxDynamicSharedMemorySize, SMB);
    cudaFuncSetAttribute(gemm_mma<ERELU2>, cudaFuncAttributeMaxDynamicSharedMemorySize, SMB);
    cudaFuncSetAttribute(gemm_mma<ERKV>,   cudaFuncAttributeMaxDynamicSharedMemorySize, SMB);
    cudaFuncSetAttribute(gemm_mma<EADD>,   cudaFuncAttributeMaxDynamicSharedMemorySize, SMB);
    cudaFuncSetAttribute(gemm_mma<ECMFIN>, cudaFuncAttributeMaxDynamicSharedMemorySize, SMB);

    // launch 0: all weight prep in one kernel
    split_all_kernel<<<2048, 256>>>(
        tm_value_w, tm_recept_w, sa_v_w, sa_o_w, tm_out_w, cm_recept_w,
        wvh, wvl, wrh, wrl, wsvh, wsvl, woh, wol, wtoh, wtol, wcrh, wcrl,
        cm_key_w, wckh, wckl, cm_value_w, wcvh, wcvl,
        sa_q_w, sa_k_w, wqkh, wqkl, sa_q_b, sa_k_b, qkb);

    // 1-2: norms/mix
    rmsnorm_kernel<<<N_, 256>>>(x, norm1_w, x1, x1h, x1l);
    mix2_kernel<<<N_, 256>>>(x1, tm_mix_v, tm_mix_r, xah, xal, xbh, xbl);

    dim3 gDD(8, 64, 1);
    // 3: qk projection (packed)
    gemm_mma<EPLB><<<dim3(1,64,1), 256, SMB>>>(x1h, x1l, D_, wqkh, wqkl, D_,
        qkb, nullptr, nullptr, nullptr, qkh, qkl, 128, D_, 1.f, 0, 0, 0);
    // 4: v
    gemm_mma<EF32><<<gDD, 256, SMB>>>(xah, xal, D_, wvh, wvl, D_,
        nullptr, nullptr, nullptr, v, nullptr, nullptr, D_, D_, 1.f, 0, 0, 0);
    // 5: r   <-- ncu profile slot
    gemm_mma<EF32><<<gDD, 256, SMB>>>(xbh, xbl, D_, wrh, wrl, D_,
        nullptr, nullptr, nullptr, r, nullptr, nullptr, D_, D_, 1.f, 0, 0, 0);
    // 6: Vsa
    gemm_mma<EF32><<<gDD, 256, SMB>>>(x1h, x1l, D_, wsvh, wsvl, D_,
        sa_v_b, nullptr, nullptr, Vsa, nullptr, nullptr, D_, D_, 1.f, 0, 0, 0);

    // 7: scores[b] = Q @ K^T / 8
    gemm_mma<EF32><<<dim3(32,32,2), 256, SMB>>>(qkh, qkl, 128, qkh + 64, qkl + 64, 128,
        nullptr, nullptr, nullptr, sc, nullptr, nullptr, S_, 64, 0.125f,
        (long long)S_*128, (long long)S_*128, (long long)S_*S_);

    // 8: topk + softmax + gather
    topk_attn_kernel<<<N_, 256>>>(sc, Vsa, aph, apl);

    // 9-10: attention out + residual
    gemm_mma<ERKV><<<gDD, 256, SMB>>>(aph, apl, D_, woh, wol, D_,
        sa_o_b, v, r, nullptr, rkh, rkl, D_, D_, 1.f, 0, 0, 0);
    gemm_mma<EADD><<<gDD, 256, SMB>>>(rkh, rkl, D_, wtoh, wtol, D_,
        nullptr, x, nullptr, xmid, nullptr, nullptr, D_, D_, 1.f, 0, 0, 0);

    // ---- channel-mix ----
    rmsnorm_kernel<<<N_, 256>>>(xmid, norm2_w, x2, nullptr, nullptr);
    mix2_kernel<<<N_, 256>>>(x2, cm_mix_k, cm_mix_r, xah, xal, xbh, xbl);

    gemm_mma<ERELU2><<<dim3(32,64,1), 256, SMB>>>(xah, xal, D_, wckh, wckl, D_,
        nullptr, nullptr, nullptr, nullptr, kch, kcl, DI_, D_, 1.f, 0, 0, 0);
    gemm_mma<EF32><<<gDD, 256, SMB>>>(xbh, xbl, D_, wcrh, wcrl, D_,
        nullptr, nullptr, nullptr, r2, nullptr, nullptr, D_, D_, 1.f, 0, 0, 0);
    gemm_mma<ECMFIN><<<gDD, 256, SMB>>>(kch, kcl, DI_, wcvh, wcvl, DI_,
        nullptr, xmid, r2, out, nullptr, nullptr, D_, DI_, 1.f, 0, 0, 0);
}

// round 10
// speedup vs baseline: 2.2737x; 1.0389x over previous
#include <cuda_runtime.h>
#include <cuda_bf16.h>
#include <math.h>
#include <stdint.h>

#define D_    1024
#define A_    64
#define TOPK_ 32
#define B_    2
#define S_    4096
#define N_    (B_ * S_)
#define DI_   4096

typedef __nv_bfloat16 bf16;

// ---------------------------------------------------------------------------
// Device-global scratch
// ---------------------------------------------------------------------------
__device__ __align__(256) float g_x1[N_ * D_];
__device__ __align__(256) float g_vr[2 * N_ * D_];          // v then r
__device__ __align__(256) float g_Vsa[N_ * D_];
__device__ __align__(256) float g_scores[(long long)B_ * S_ * S_];
__device__ __align__(256) float g_xmid[N_ * D_];
__device__ __align__(256) float g_x2[N_ * D_];
__device__ __align__(256) float g_r2[N_ * D_];
__device__ __align__(256) float g_bias[1152];

__device__ __align__(256) bf16 g_x1h[N_ * D_],  g_x1l[N_ * D_];
__device__ __align__(256) bf16 g_xabh[2 * N_ * D_], g_xabl[2 * N_ * D_];   // xa | xb
__device__ __align__(256) bf16 g_qkh[N_ * 128], g_qkl[N_ * 128];
__device__ __align__(256) bf16 g_aph[N_ * D_],  g_apl[N_ * D_];
__device__ __align__(256) bf16 g_rkh[N_ * D_],  g_rkl[N_ * D_];
__device__ __align__(256) bf16 g_kch[(long long)N_ * DI_], g_kcl[(long long)N_ * DI_];

// hi/lo bf16 weights
__device__ __align__(256) bf16 g_wvrh[2 * D_ * D_],  g_wvrl[2 * D_ * D_];
__device__ __align__(256) bf16 g_wqksvh[1152 * D_],  g_wqksvl[1152 * D_];
__device__ __align__(256) bf16 g_woh[D_ * D_],   g_wol[D_ * D_];
__device__ __align__(256) bf16 g_wtoh[D_ * D_],  g_wtol[D_ * D_];
__device__ __align__(256) bf16 g_wcrh[D_ * D_],  g_wcrl[D_ * D_];
__device__ __align__(256) bf16 g_wckh[DI_ * D_], g_wckl[DI_ * D_];
__device__ __align__(256) bf16 g_wcvh[(long long)D_ * DI_], g_wcvl[(long long)D_ * DI_];

// ---------------------------------------------------------------------------
// Helpers
// ---------------------------------------------------------------------------
__device__ __forceinline__ float sigmoidf_(float x) { return 1.f / (1.f + expf(-x)); }

__device__ __forceinline__ void splitstore(bf16* H, bf16* L, long long idx, float v)
{
    bf16 h = __float2bfloat16(v);
    H[idx] = h;
    L[idx] = __float2bfloat16(v - __bfloat162float(h));
}

__device__ __forceinline__ void store_planes4(bf16* H, bf16* L, long long idx, float4 v)
{
    splitstore(H, L, idx + 0, v.x); splitstore(H, L, idx + 1, v.y);
    splitstore(H, L, idx + 2, v.z); splitstore(H, L, idx + 3, v.w);
}

__device__ __forceinline__ uint32_t smem_u32(const void* p)
{
    uint32_t a;
    asm("{ .reg .u64 t; cvta.to.shared.u64 t, %1; cvt.u32.u64 %0, t; }" : "=r"(a) : "l"(p));
    return a;
}
__device__ __forceinline__ void cp16(uint32_t s, const void* g)
{
    asm volatile("cp.async.cg.shared.global [%0], [%1], 16;" :: "r"(s), "l"(g));
}
__device__ __forceinline__ void ldsm4(uint32_t* r, uint32_t addr)
{
    asm volatile("ldmatrix.sync.aligned.m8n8.x4.shared.b16 {%0,%1,%2,%3}, [%4];"
                 : "=r"(r[0]), "=r"(r[1]), "=r"(r[2]), "=r"(r[3]) : "r"(addr));
}
__device__ __forceinline__ void mma16816(float* c, const uint32_t* a,
                                         uint32_t b0, uint32_t b1)
{
    asm volatile(
        "mma.sync.aligned.m16n8k16.row.col.f32.bf16.bf16.f32 "
        "{%0,%1,%2,%3},{%4,%5,%6,%7},{%8,%9},{%0,%1,%2,%3};"
        : "+f"(c[0]), "+f"(c[1]), "+f"(c[2]), "+f"(c[3])
        : "r"(a[0]), "r"(a[1]), "r"(a[2]), "r"(a[3]), "r"(b0), "r"(b1));
}

#define EF32    0
#define EQKVSA  1   /* col<128: planes+bias (qk); else f32+bias (Vsa) */
#define ERELU2  2   /* planes, relu(acc)^2                */
#define ERKV    3   /* planes, sigmoid(E1)*(acc+bias+E0)  */
#define EADD    4   /* f32, acc+E0                        */
#define ECMFIN  5   /* f32, E0 + sigmoid(E1)*acc          */

// ---------------------------------------------------------------------------
// bf16 split-precision NT GEMM (R5 numerics):
//   C = Ah*Bh + Al*Bh + Ah*Bl, fp32 accum.
// CTA 128x128, BK=32, 2-stage cp.async (4 planes, 80KB -> 2 CTAs/SM).
// ---------------------------------------------------------------------------
#define ROWB   80
#define PLANE  (128 * ROWB)        /* 10240 B */
#define STAGEB (4 * PLANE)         /* 40960 B */

template<int EPI>
__global__ __launch_bounds__(256, 2)
void gemm_mma(const bf16* __restrict__ Ah, const bf16* __restrict__ Al, int lda,
              const bf16* __restrict__ Bh, const bf16* __restrict__ Bl, int ldb,
              const float* __restrict__ bias, const float* __restrict__ E0,
              const float* __restrict__ E1,
              float* __restrict__ Cf, bf16* __restrict__ Ch, bf16* __restrict__ Cl,
              int ldc, int K, float scale,
              long long sA, long long sB, long long sC)
{
    extern __shared__ __align__(256) char smem[];

    Ah += (long long)blockIdx.z * sA;  Al += (long long)blockIdx.z * sA;
    Bh += (long long)blockIdx.z * sB;  Bl += (long long)blockIdx.z * sB;
    const long long zC = (long long)blockIdx.z * sC;

    const int tid  = threadIdx.x;
    const int lane = tid & 31;
    const int wid  = tid >> 5;
    const int wm   = wid & 1;
    const int wn   = wid >> 1;
    const int row0 = blockIdx.y * 128;
    const int col0 = blockIdx.x * 128;

    const uint32_t sbase = smem_u32(smem);
    const int NC = K >> 5;

    float acc[4][4][4];
    #pragma unroll
    for (int mf = 0; mf < 4; mf++)
        #pragma unroll
        for (int nf = 0; nf < 4; nf++)
            #pragma unroll
            for (int e = 0; e < 4; e++) acc[mf][nf][e] = 0.f;

    auto load_stage = [&](int c, int s) {
        uint32_t st = sbase + s * STAGEB;
        int k0 = c << 5;
        const bf16* srcs[4] = { Ah, Al, Bh, Bl };
        #pragma unroll
        for (int p = 0; p < 4; p++) {
            int base = (p < 2) ? row0 : col0;
            int ld   = (p < 2) ? lda : ldb;
            const bf16* sp = srcs[p] + (long long)base * ld + k0;
            uint32_t db = st + p * PLANE;
            #pragma unroll
            for (int i = tid; i < 512; i += 256) {
                int rr = i >> 2, ch = i & 3;
                cp16(db + rr * ROWB + ch * 16, sp + (long long)rr * ld + ch * 8);
            }
        }
        asm volatile("cp.async.commit_group;" ::: "memory");
    };

    auto load_frags = [&](uint32_t st, int kk,
                          uint32_t (&aH)[4][4], uint32_t (&aL)[4][4],
                          uint32_t (&bH)[2][4], uint32_t (&bL)[2][4]) {
        int chunk = (kk * 2 + (lane >> 4)) * 16;
        int arow  = wm * 64 + (lane & 15);
        #pragma unroll
        for (int mf = 0; mf < 4; mf++) {
            uint32_t off = (uint32_t)(arow + mf * 16) * ROWB + chunk;
            ldsm4(aH[mf], st + off);
            ldsm4(aL[mf], st + PLANE + off);
        }
        int brow = wn * 32 + (lane & 7) + ((lane >> 3) & 1) * 8;
        #pragma unroll
        for (int np = 0; np < 2; np++) {
            uint32_t off = (uint32_t)(brow + np * 16) * ROWB + chunk;
            ldsm4(bH[np], st + 2 * PLANE + off);
            ldsm4(bL[np], st + 3 * PLANE + off);
        }
    };

    auto do_mma = [&](uint32_t (&aH)[4][4], uint32_t (&aL)[4][4],
                      uint32_t (&bH)[2][4], uint32_t (&bL)[2][4]) {
        #pragma unroll
        for (int mf = 0; mf < 4; mf++)
            #pragma unroll
            for (int nf = 0; nf < 4; nf++) {
                int np = nf >> 1, sl = nf & 1;
                mma16816(acc[mf][nf], aH[mf], bH[np][sl], bH[np][2 + sl]);
            }
        #pragma unroll
        for (int mf = 0; mf < 4; mf++)
            #pragma unroll
            for (int nf = 0; nf < 4; nf++) {
                int np = nf >> 1, sl = nf & 1;
                mma16816(acc[mf][nf], aL[mf], bH[np][sl], bH[np][2 + sl]);
            }
        #pragma unroll
        for (int mf = 0; mf < 4; mf++)
            #pragma unroll
            for (int nf = 0; nf < 4; nf++) {
                int np = nf >> 1, sl = nf & 1;
                mma16816(acc[mf][nf], aH[mf], bL[np][sl], bL[np][2 + sl]);
            }
    };

    load_stage(0, 0);
    if (NC > 1) load_stage(1, 1);

    for (int c = 0; c < NC; c++) {
        int s = c & 1;
        if (c + 1 < NC) asm volatile("cp.async.wait_group 1;" ::: "memory");
        else            asm volatile("cp.async.wait_group 0;" ::: "memory");
        __syncthreads();
        uint32_t st = sbase + s * STAGEB;

        uint32_t aH[4][4], aL[4][4], bH[2][4], bL[2][4];
        load_frags(st, 0, aH, aL, bH, bL);
        do_mma(aH, aL, bH, bL);

        load_frags(st, 1, aH, aL, bH, bL);
        __syncthreads();
        if (c + 2 < NC) load_stage(c + 2, s);
        do_mma(aH, aL, bH, bL);
    }

    // ---- epilogue ----
    #pragma unroll
    for (int mf = 0; mf < 4; mf++) {
        #pragma unroll
        for (int nf = 0; nf < 4; nf++) {
            int rA = row0 + wm * 64 + mf * 16 + (lane >> 2);
            int cB = col0 + wn * 32 + nf * 8 + (lane & 3) * 2;
            #pragma unroll
            for (int h = 0; h < 2; h++) {
                int rr = rA + h * 8;
                long long idx = (long long)rr * ldc + cB + zC;
                float v0 = acc[mf][nf][h * 2 + 0];
                float v1 = acc[mf][nf][h * 2 + 1];
                if (EPI == EF32) {
                    *(float2*)(Cf + idx) = make_float2(v0 * scale, v1 * scale);
                } else if (EPI == EQKVSA) {
                    if (col0 < 128) {
                        long long qi = (long long)rr * 128 + cB;
                        splitstore(Ch, Cl, qi,     v0 + bias[cB]);
                        splitstore(Ch, Cl, qi + 1, v1 + bias[cB + 1]);
                    } else {
                        long long vi = (long long)rr * 1024 + (cB - 128);
                        *(float2*)(Cf + vi) =
                            make_float2(v0 + bias[cB], v1 + bias[cB + 1]);
                    }
                } else if (EPI == ERELU2) {
                    float u0 = fmaxf(v0, 0.f), u1 = fmaxf(v1, 0.f);
                    splitstore(Ch, Cl, idx,     u0 * u0);
                    splitstore(Ch, Cl, idx + 1, u1 * u1);
                } else if (EPI == ERKV) {
                    splitstore(Ch, Cl, idx,
                               sigmoidf_(E1[idx]) * (v0 + bias[cB] + E0[idx]));
                    splitstore(Ch, Cl, idx + 1,
                               sigmoidf_(E1[idx + 1]) * (v1 + bias[cB + 1] + E0[idx + 1]));
                } else if (EPI == EADD) {
                    *(float2*)(Cf + idx) = make_float2(v0 + E0[idx], v1 + E0[idx + 1]);
                } else { // ECMFIN
                    float o0 = E0[idx]     + sigmoidf_(E1[idx])     * v0;
                    float o1 = E0[idx + 1] + sigmoidf_(E1[idx + 1]) * v1;
                    *(float2*)(Cf + idx) = make_float2(o0, o1);
                }
            }
        }
    }
}

// ---------------------------------------------------------------------------
// Fused weight prep: hi/lo bf16 planes for all weights, one launch.
// FIX vs R6/R9: QK/SV row pointers advance in FLOAT4-correct units
// (row * 1024 floats per row, not row * 256).
// ---------------------------------------------------------------------------
__global__ __launch_bounds__(256)
void split_all_kernel(const float* tmv, const float* tmr, const float* qw,
                      const float* kw,  const float* svw, const float* ow,
                      const float* tow, const float* crw, const float* ckw,
                      const float* cvw,
                      const float* qb, const float* kb, const float* svb,
                      float* bias)
{
    const long long t0 = blockIdx.x * 256 + threadIdx.x;
    const long long st = (long long)gridDim.x * 256;
    const int DD4 = D_ * D_ / 4;

    if (blockIdx.x == 0)
        for (int t = threadIdx.x; t < 1152; t += 256)
            bias[t] = (t < 64) ? qb[t] : (t < 128) ? kb[t - 64] : svb[t - 128];

    for (long long i = t0; i < DD4; i += st)
        store_planes4(g_wvrh, g_wvrl, i * 4, ((const float4*)tmv)[i]);
    for (long long i = t0; i < DD4; i += st)
        store_planes4(g_wvrh + D_*D_, g_wvrl + D_*D_, i * 4, ((const float4*)tmr)[i]);
    for (long long i = t0; i < 1152 * 256; i += st) {
        int row = (int)(i >> 8), c = (int)(i & 255);
        const float* src = (row < 64)  ? qw  + (long long)row * 1024
                         : (row < 128) ? kw  + (long long)(row - 64) * 1024
                                       : svw + (long long)(row - 128) * 1024;
        store_planes4(g_wqksvh, g_wqksvl, i * 4, ((const float4*)src)[c]);
    }
    for (long long i = t0; i < DD4; i += st)
        store_planes4(g_woh,  g_wol,  i * 4, ((const float4*)ow)[i]);
    for (long long i = t0; i < DD4; i += st)
        store_planes4(g_wtoh, g_wtol, i * 4, ((const float4*)tow)[i]);
    for (long long i = t0; i < DD4; i += st)
        store_planes4(g_wcrh, g_wcrl, i * 4, ((const float4*)crw)[i]);
    for (long long i = t0; i < (long long)DI_ * D_ / 4; i += st)
        store_planes4(g_wckh, g_wckl, i * 4, ((const float4*)ckw)[i]);
    for (long long i = t0; i < (long long)D_ * DI_ / 4; i += st)
        store_planes4(g_wcvh, g_wcvl, i * 4, ((const float4*)cvw)[i]);
}

// ---------------------------------------------------------------------------
// RMSNorm / mix / topk
// ---------------------------------------------------------------------------
__global__ __launch_bounds__(256)
void rmsnorm_kernel(const float* __restrict__ x, const float* __restrict__ w,
                    float* __restrict__ outf, bf16* __restrict__ oh, bf16* __restrict__ ol)
{
    int n = blockIdx.x, tid = threadIdx.x;
    float4 xv = ((const float4*)(x + (long)n * D_))[tid];
    float ss = xv.x*xv.x + xv.y*xv.y + xv.z*xv.z + xv.w*xv.w;
    #pragma unroll
    for (int off = 16; off; off >>= 1) ss += __shfl_xor_sync(~0u, ss, off);
    __shared__ float wss[8];  __shared__ float s_scale;
    if ((tid & 31) == 0) wss[tid >> 5] = ss;
    __syncthreads();
    if (tid == 0) {
        float tot = 0.f;
        #pragma unroll
        for (int i = 0; i < 8; i++) tot += wss[i];
        s_scale = 1.f / (sqrtf(tot / (float)D_) + 1e-8f);
    }
    __syncthreads();
    float sc = s_scale;
    float4 wv = ((const float4*)w)[tid];
    float4 ov = make_float4(xv.x*wv.x*sc, xv.y*wv.y*sc, xv.z*wv.z*sc, xv.w*wv.w*sc);
    long long idx = (long long)n * D_ + tid * 4;
    ((float4*)(outf))[idx >> 2] = ov;
    if (oh) store_planes4(oh, ol, idx, ov);
}

__global__ __launch_bounds__(256)
void mix2_kernel(const float* __restrict__ x,
                 const float* __restrict__ mA, const float* __restrict__ mB,
                 bf16* __restrict__ ah, bf16* __restrict__ al,
                 bf16* __restrict__ bh, bf16* __restrict__ bl)
{
    int n = blockIdx.x, tid = threadIdx.x;
    int prev = ((n & (S_ - 1)) == 0) ? n : n - 1;
    float4 cur = ((const float4*)(x + (long)n    * D_))[tid];
    float4 pv  = ((const float4*)(x + (long)prev * D_))[tid];
    float4 ma  = ((const float4*)mA)[tid];
    float4 mb  = ((const float4*)mB)[tid];
    long long idx = (long long)n * D_ + tid * 4;
    float4 oa = make_float4(cur.x*ma.x + pv.x*(1.f-ma.x), cur.y*ma.y + pv.y*(1.f-ma.y),
                            cur.z*ma.z + pv.z*(1.f-ma.z), cur.w*ma.w + pv.w*(1.f-ma.w));
    float4 ob = make_float4(cur.x*mb.x + pv.x*(1.f-mb.x), cur.y*mb.y + pv.y*(1.f-mb.y),
                            cur.z*mb.z + pv.z*(1.f-mb.z), cur.w*mb.w + pv.w*(1.f-mb.w));
    store_planes4(ah, al, idx, oa);
    store_planes4(bh, bl, idx, ob);
}

__global__ __launch_bounds__(256)
void topk_attn_kernel(const float* __restrict__ scores, const float* __restrict__ V,
                      bf16* __restrict__ oh, bf16* __restrict__ ol)
{
    int q = blockIdx.x, b = q >> 12, qs = q & (S_ - 1), tid = threadIdx.x;
    const float* srow = scores + (long long)b * S_ * S_ + (long long)qs * S_;
    float s[16];
    #pragma unroll
    for (int i = 0; i < 16; i++) s[i] = srow[i * 256 + tid];

    __shared__ float wv[8]; __shared__ int wi[8];
    __shared__ float top_val[TOPK_]; __shared__ int top_idx[TOPK_];
    __shared__ int s_win;
    const float NEG = -__int_as_float(0x7f800000);

    for (int t = 0; t < TOPK_; t++) {
        float best = NEG; int bi = 0;
        #pragma unroll
        for (int i = 0; i < 16; i++) if (s[i] > best) { best = s[i]; bi = i; }
        int gidx = bi * 256 + tid;
        #pragma unroll
        for (int off = 16; off; off >>= 1) {
            float ov = __shfl_down_sync(~0u, best, off);
            int   oi = __shfl_down_sync(~0u, gidx, off);
            if (ov > best) { best = ov; gidx = oi; }
        }
        if ((tid & 31) == 0) { wv[tid >> 5] = best; wi[tid >> 5] = gidx; }
        __syncthreads();
        if (tid == 0) {
            float bb = wv[0]; int bbi = wi[0];
            #pragma unroll
            for (int w = 1; w < 8; w++) if (wv[w] > bb) { bb = wv[w]; bbi = wi[w]; }
            top_val[t] = bb; top_idx[t] = bbi; s_win = bbi;
        }
        __syncthreads();
        int win = s_win;
        if ((win & 255) == tid) s[win >> 8] = NEG;
    }

    __shared__ float wts[TOPK_];
    if (tid < 32) {
        float e = expf(top_val[tid] - top_val[0]);
        float ssum = e;
        #pragma unroll
        for (int off = 16; off; off >>= 1) ssum += __shfl_xor_sync(~0u, ssum, off);
        wts[tid] = e / ssum;
    }
    __syncthreads();

    const float* Vb = V + (long long)b * S_ * D_;
    float4 acc = make_float4(0.f, 0.f, 0.f, 0.f);
    #pragma unroll
    for (int t = 0; t < TOPK_; t++) {
        float w = wts[t];
        float4 vr = *(const float4*)&Vb[(long long)top_idx[t] * D_ + tid * 4];
        acc.x += w*vr.x; acc.y += w*vr.y; acc.z += w*vr.z; acc.w += w*vr.w;
    }
    store_planes4(oh, ol, (long long)q * D_ + tid * 4, acc);
}

// ---------------------------------------------------------------------------
// Host
// ---------------------------------------------------------------------------
template <typename T> static void* symaddr(T& sym)
{ void* p = nullptr; cudaGetSymbolAddress(&p, sym); return p; }

extern "C" void kernel_launch(void* const* d_in, const int* in_sizes, int n_in,
                              void* d_out, int out_size)
{
    const float* x        = (const float*)d_in[0];
    const float* norm1_w  = (const float*)d_in[1];
    const float* tm_mix_v = (const float*)d_in[3];
    const float* tm_mix_r = (const float*)d_in[4];
    const float* tm_value_w  = (const float*)d_in[6];
    const float* tm_recept_w = (const float*)d_in[7];
    const float* tm_out_w = (const float*)d_in[8];
    const float* sa_q_w   = (const float*)d_in[9];
    const float* sa_q_b   = (const float*)d_in[10];
    const float* sa_k_w   = (const float*)d_in[11];
    const float* sa_k_b   = (const float*)d_in[12];
    const float* sa_v_w   = (const float*)d_in[13];
    const float* sa_v_b   = (const float*)d_in[14];
    const float* sa_o_w   = (const float*)d_in[15];
    const float* sa_o_b   = (const float*)d_in[16];
    const float* norm2_w  = (const float*)d_in[17];
    const float* cm_mix_k = (const float*)d_in[18];
    const float* cm_mix_r = (const float*)d_in[19];
    const float* cm_key_w = (const float*)d_in[20];
    const float* cm_recept_w = (const float*)d_in[21];
    const float* cm_value_w  = (const float*)d_in[22];
    float* out = (float*)d_out;

    float* x1   = (float*)symaddr(g_x1);
    float* vr   = (float*)symaddr(g_vr);
    float* Vsa  = (float*)symaddr(g_Vsa);
    float* sc   = (float*)symaddr(g_scores);
    float* xmid = (float*)symaddr(g_xmid);
    float* x2   = (float*)symaddr(g_x2);
    float* r2   = (float*)symaddr(g_r2);
    float* bias = (float*)symaddr(g_bias);

    bf16 *x1h=(bf16*)symaddr(g_x1h),   *x1l=(bf16*)symaddr(g_x1l);
    bf16 *xabh=(bf16*)symaddr(g_xabh), *xabl=(bf16*)symaddr(g_xabl);
    bf16 *qkh=(bf16*)symaddr(g_qkh),   *qkl=(bf16*)symaddr(g_qkl);
    bf16 *aph=(bf16*)symaddr(g_aph),   *apl=(bf16*)symaddr(g_apl);
    bf16 *rkh=(bf16*)symaddr(g_rkh),   *rkl=(bf16*)symaddr(g_rkl);
    bf16 *kch=(bf16*)symaddr(g_kch),   *kcl=(bf16*)symaddr(g_kcl);
    bf16 *wvrh=(bf16*)symaddr(g_wvrh),   *wvrl=(bf16*)symaddr(g_wvrl);
    bf16 *wqksvh=(bf16*)symaddr(g_wqksvh), *wqksvl=(bf16*)symaddr(g_wqksvl);
    bf16 *woh=(bf16*)symaddr(g_woh),   *wol=(bf16*)symaddr(g_wol);
    bf16 *wtoh=(bf16*)symaddr(g_wtoh), *wtol=(bf16*)symaddr(g_wtol);
    bf16 *wcrh=(bf16*)symaddr(g_wcrh), *wcrl=(bf16*)symaddr(g_wcrl);
    bf16 *wckh=(bf16*)symaddr(g_wckh), *wckl=(bf16*)symaddr(g_wckl);
    bf16 *wcvh=(bf16*)symaddr(g_wcvh), *wcvl=(bf16*)symaddr(g_wcvl);

    const int SMB = 2 * STAGEB;   // 81920 -> 2 CTAs/SM
    cudaFuncSetAttribute(gemm_mma<EF32>,   cudaFuncAttributeMaxDynamicSharedMemorySize, SMB);
    cudaFuncSetAttribute(gemm_mma<EQKVSA>, cudaFuncAttributeMaxDynamicSharedMemorySize, SMB);
    cudaFuncSetAttribute(gemm_mma<ERELU2>, cudaFuncAttributeMaxDynamicSharedMemorySize, SMB);
    cudaFuncSetAttribute(gemm_mma<ERKV>,   cudaFuncAttributeMaxDynamicSharedMemorySize, SMB);
    cudaFuncSetAttribute(gemm_mma<EADD>,   cudaFuncAttributeMaxDynamicSharedMemorySize, SMB);
    cudaFuncSetAttribute(gemm_mma<ECMFIN>, cudaFuncAttributeMaxDynamicSharedMemorySize, SMB);

    // 0: weight prep (hi/lo planes + packing)
    split_all_kernel<<<2048, 256>>>(tm_value_w, tm_recept_w, sa_q_w, sa_k_w,
                                    sa_v_w, sa_o_w, tm_out_w, cm_recept_w,
                                    cm_key_w, cm_value_w,
                                    sa_q_b, sa_k_b, sa_v_b, bias);

    // 1-2: norm + mix
    rmsnorm_kernel<<<N_, 256>>>(x, norm1_w, x1, x1h, x1l);
    mix2_kernel<<<N_, 256>>>(x1, tm_mix_v, tm_mix_r,
                             xabh, xabl, xabh + (long long)N_*D_, xabl + (long long)N_*D_);

    // 3: merged QK + Vsa projection
    gemm_mma<EQKVSA><<<dim3(9,64,1), 256, SMB>>>(x1h, x1l, D_, wqksvh, wqksvl, D_,
        bias, nullptr, nullptr, Vsa, qkh, qkl, 1152, D_, 1.f, 0, 0, 0);

    // 4: batched v,r
    gemm_mma<EF32><<<dim3(8,64,2), 256, SMB>>>(xabh, xabl, D_, wvrh, wvrl, D_,
        nullptr, nullptr, nullptr, vr, nullptr, nullptr, D_, D_, 1.f,
        (long long)N_*D_, (long long)D_*D_, (long long)N_*D_);

    // 5: scores = Q @ K^T / 8
    gemm_mma<EF32><<<dim3(32,32,2), 256, SMB>>>(qkh, qkl, 128, qkh + 64, qkl + 64, 128,
        nullptr, nullptr, nullptr, sc, nullptr, nullptr, S_, 64, 0.125f,
        (long long)S_*128, (long long)S_*128, (long long)S_*S_);

    // 6: topk + softmax + gather
    topk_attn_kernel<<<N_, 256>>>(sc, Vsa, aph, apl);

    // 7: rkv = sigmoid(r)*(ap@o_w^T + o_b + v)
    gemm_mma<ERKV><<<dim3(8,64,1), 256, SMB>>>(aph, apl, D_, woh, wol, D_,
        sa_o_b, vr, vr + (long long)N_*D_, nullptr, rkh, rkl, D_, D_, 1.f, 0, 0, 0);
    // 8: xmid = x + rkv@tm_out^T
    gemm_mma<EADD><<<dim3(8,64,1), 256, SMB>>>(rkh, rkl, D_, wtoh, wtol, D_,
        nullptr, x, nullptr, xmid, nullptr, nullptr, D_, D_, 1.f, 0, 0, 0);

    // 9-10: channel-mix norm + mix
    rmsnorm_kernel<<<N_, 256>>>(xmid, norm2_w, x2, nullptr, nullptr);
    mix2_kernel<<<N_, 256>>>(x2, cm_mix_k, cm_mix_r,
                             xabh, xabl, xabh + (long long)N_*D_, xabl + (long long)N_*D_);

    // 11: kc = relu(xa@ck^T)^2
    gemm_mma<ERELU2><<<dim3(32,64,1), 256, SMB>>>(xabh, xabl, D_, wckh, wckl, D_,
        nullptr, nullptr, nullptr, nullptr, kch, kcl, DI_, D_, 1.f, 0, 0, 0);
    // 12: r2 = xb@cr^T
    gemm_mma<EF32><<<dim3(8,64,1), 256, SMB>>>(xabh + (long long)N_*D_,
        xabl + (long long)N_*D_, D_, wcrh, wcrl, D_,
        nullptr, nullptr, nullptr, r2, nullptr, nullptr, D_, D_, 1.f, 0, 0, 0);
    // 13: out = xmid + sigmoid(r2)*(kc@cv^T)
    gemm_mma<ECMFIN><<<dim3(8,64,1), 256, SMB>>>(kch, kcl, DI_, wcvh, wcvl, DI_,
        nullptr, xmid, r2, out, nullptr, nullptr, D_, DI_, 1.f, 0, 0, 0);
}

// round 13
// speedup vs baseline: 2.3365x; 1.0276x over previous
#include <cuda_runtime.h>
#include <cuda_fp16.h>
#include <math.h>
#include <stdint.h>

#define D_    1024
#define A_    64
#define TOPK_ 32
#define B_    2
#define S_    4096
#define N_    (B_ * S_)
#define DI_   4096

typedef __half fp16;

// ---------------------------------------------------------------------------
// Device-global scratch
// ---------------------------------------------------------------------------
__device__ __align__(256) float g_vr[2 * N_ * D_];          // v then r
__device__ __align__(256) float g_Vsa[N_ * D_];
__device__ __align__(256) float g_scores[(long long)B_ * S_ * S_];
__device__ __align__(256) float g_xmid[N_ * D_];
__device__ __align__(256) float g_r2[N_ * D_];
__device__ __align__(256) float g_bias[1152];

__device__ __align__(256) fp16 g_x1h[N_ * D_],  g_x1l[N_ * D_];
__device__ __align__(256) fp16 g_xabh[2 * N_ * D_], g_xabl[2 * N_ * D_];   // xa | xb
__device__ __align__(256) fp16 g_qkh[N_ * 128], g_qkl[N_ * 128];
__device__ __align__(256) fp16 g_aph[N_ * D_],  g_apl[N_ * D_];
__device__ __align__(256) fp16 g_rkh[N_ * D_],  g_rkl[N_ * D_];
__device__ __align__(256) fp16 g_kch[(long long)N_ * DI_], g_kcl[(long long)N_ * DI_];

// hi/lo fp16 weights
__device__ __align__(256) fp16 g_wvrh[2 * D_ * D_],  g_wvrl[2 * D_ * D_];
__device__ __align__(256) fp16 g_wqksvh[1152 * D_],  g_wqksvl[1152 * D_];
__device__ __align__(256) fp16 g_woh[D_ * D_],   g_wol[D_ * D_];
__device__ __align__(256) fp16 g_wtoh[D_ * D_],  g_wtol[D_ * D_];
__device__ __align__(256) fp16 g_wckcrh[5120 * D_], g_wckcrl[5120 * D_];   // [ck;cr]
__device__ __align__(256) fp16 g_wcvh[(long long)D_ * DI_], g_wcvl[(long long)D_ * DI_];

// ---------------------------------------------------------------------------
// Helpers
// ---------------------------------------------------------------------------
__device__ __forceinline__ float sigmoidf_(float x) { return 1.f / (1.f + expf(-x)); }

__device__ __forceinline__ void splitstore(fp16* H, fp16* L, long long idx, float v)
{
    fp16 h = __float2half_rn(v);
    H[idx] = h;
    L[idx] = __float2half_rn(v - __half2float(h));
}

__device__ __forceinline__ void store_planes4(fp16* H, fp16* L, long long idx, float4 v)
{
    __half2 h01 = __floats2half2_rn(v.x, v.y);
    __half2 h23 = __floats2half2_rn(v.z, v.w);
    float h0f = __half2float(__low2half(h01)),  h1f = __half2float(__high2half(h01));
    float h2f = __half2float(__low2half(h23)),  h3f = __half2float(__high2half(h23));
    __half2 l01 = __floats2half2_rn(v.x - h0f, v.y - h1f);
    __half2 l23 = __floats2half2_rn(v.z - h2f, v.w - h3f);
    ((__half2*)(H + idx))[0] = h01; ((__half2*)(H + idx))[1] = h23;
    ((__half2*)(L + idx))[0] = l01; ((__half2*)(L + idx))[1] = l23;
}

__device__ __forceinline__ uint32_t smem_u32(const void* p)
{
    uint32_t a;
    asm("{ .reg .u64 t; cvta.to.shared.u64 t, %1; cvt.u32.u64 %0, t; }" : "=r"(a) : "l"(p));
    return a;
}
__device__ __forceinline__ void cp16(uint32_t s, const void* g)
{
    asm volatile("cp.async.cg.shared.global [%0], [%1], 16;" :: "r"(s), "l"(g));
}
__device__ __forceinline__ void ldsm4(uint32_t* r, uint32_t addr)
{
    asm volatile("ldmatrix.sync.aligned.m8n8.x4.shared.b16 {%0,%1,%2,%3}, [%4];"
                 : "=r"(r[0]), "=r"(r[1]), "=r"(r[2]), "=r"(r[3]) : "r"(addr));
}
__device__ __forceinline__ void mma16816(float* c, const uint32_t* a,
                                         uint32_t b0, uint32_t b1)
{
    asm volatile(
        "mma.sync.aligned.m16n8k16.row.col.f32.f16.f16.f32 "
        "{%0,%1,%2,%3},{%4,%5,%6,%7},{%8,%9},{%0,%1,%2,%3};"
        : "+f"(c[0]), "+f"(c[1]), "+f"(c[2]), "+f"(c[3])
        : "r"(a[0]), "r"(a[1]), "r"(a[2]), "r"(a[3]), "r"(b0), "r"(b1));
}

#define EF32    0
#define EQKVSA  1   /* col<128: planes+bias (qk); else f32+bias (Vsa) */
#define ERKV    3   /* planes, sigmoid(E1)*(acc+bias+E0)  */
#define EADD    4   /* f32, acc+E0                        */
#define ECMFIN  5   /* f32, E0 + sigmoid(E1)*acc          */
#define ERELU2  6   /* planes, relu(acc)^2                */

// ---------------------------------------------------------------------------
// fp16 split NT GEMM on mma.sync, 3-pass: C = Ah*Bh + Al*Bh + Ah*Bl
// (omitted Al*Bl term ~2^-24 — near-exact). fp32 accum.
// CTA 128x128, BK=32, 2-stage cp.async (4 planes, 80KB -> 2 CTAs/SM).
// ---------------------------------------------------------------------------
#define ROWB   80
#define PLANE  (128 * ROWB)        /* 10240 B */
#define STAGEB (4 * PLANE)         /* 40960 B */

template<int EPI>
__global__ __launch_bounds__(256, 2)
void gemm_mma(const fp16* __restrict__ Ah, const fp16* __restrict__ Al, int lda,
              const fp16* __restrict__ Bh, const fp16* __restrict__ Bl, int ldb,
              const float* __restrict__ bias, const float* __restrict__ E0,
              const float* __restrict__ E1,
              float* __restrict__ Cf, fp16* __restrict__ Ch, fp16* __restrict__ Cl,
              int ldc, int K, float scale,
              long long sA, long long sB, long long sC)
{
    extern __shared__ __align__(256) char smem[];

    Ah += (long long)blockIdx.z * sA;  Al += (long long)blockIdx.z * sA;
    Bh += (long long)blockIdx.z * sB;  Bl += (long long)blockIdx.z * sB;
    const long long zC = (long long)blockIdx.z * sC;

    const int tid  = threadIdx.x;
    const int lane = tid & 31;
    const int wid  = tid >> 5;
    const int wm   = wid & 1;
    const int wn   = wid >> 1;
    const int row0 = blockIdx.y * 128;
    const int col0 = blockIdx.x * 128;

    const uint32_t sbase = smem_u32(smem);
    const int NC = K >> 5;

    float acc[4][4][4];
    #pragma unroll
    for (int mf = 0; mf < 4; mf++)
        #pragma unroll
        for (int nf = 0; nf < 4; nf++)
            #pragma unroll
            for (int e = 0; e < 4; e++) acc[mf][nf][e] = 0.f;

    auto load_stage = [&](int c, int s) {
        uint32_t st = sbase + s * STAGEB;
        int k0 = c << 5;
        const fp16* srcs[4] = { Ah, Al, Bh, Bl };
        #pragma unroll
        for (int p = 0; p < 4; p++) {
            int base = (p < 2) ? row0 : col0;
            int ld   = (p < 2) ? lda : ldb;
            const fp16* sp = srcs[p] + (long long)base * ld + k0;
            uint32_t db = st + p * PLANE;
            #pragma unroll
            for (int i = tid; i < 512; i += 256) {
                int rr = i >> 2, ch = i & 3;
                cp16(db + rr * ROWB + ch * 16, sp + (long long)rr * ld + ch * 8);
            }
        }
        asm volatile("cp.async.commit_group;" ::: "memory");
    };

    auto load_frags = [&](uint32_t st, int kk,
                          uint32_t (&aH)[4][4], uint32_t (&aL)[4][4],
                          uint32_t (&bH)[2][4], uint32_t (&bL)[2][4]) {
        int chunk = (kk * 2 + (lane >> 4)) * 16;
        int arow  = wm * 64 + (lane & 15);
        #pragma unroll
        for (int mf = 0; mf < 4; mf++) {
            uint32_t off = (uint32_t)(arow + mf * 16) * ROWB + chunk;
            ldsm4(aH[mf], st + off);
            ldsm4(aL[mf], st + PLANE + off);
        }
        int brow = wn * 32 + (lane & 7) + ((lane >> 3) & 1) * 8;
        #pragma unroll
        for (int np = 0; np < 2; np++) {
            uint32_t off = (uint32_t)(brow + np * 16) * ROWB + chunk;
            ldsm4(bH[np], st + 2 * PLANE + off);
            ldsm4(bL[np], st + 3 * PLANE + off);
        }
    };

    auto do_mma = [&](uint32_t (&aH)[4][4], uint32_t (&aL)[4][4],
                      uint32_t (&bH)[2][4], uint32_t (&bL)[2][4]) {
        #pragma unroll
        for (int mf = 0; mf < 4; mf++)
            #pragma unroll
            for (int nf = 0; nf < 4; nf++) {
                int np = nf >> 1, sl = nf & 1;
                mma16816(acc[mf][nf], aH[mf], bH[np][sl], bH[np][2 + sl]);
            }
        #pragma unroll
        for (int mf = 0; mf < 4; mf++)
            #pragma unroll
            for (int nf = 0; nf < 4; nf++) {
                int np = nf >> 1, sl = nf & 1;
                mma16816(acc[mf][nf], aL[mf], bH[np][sl], bH[np][2 + sl]);
            }
        #pragma unroll
        for (int mf = 0; mf < 4; mf++)
            #pragma unroll
            for (int nf = 0; nf < 4; nf++) {
                int np = nf >> 1, sl = nf & 1;
                mma16816(acc[mf][nf], aH[mf], bL[np][sl], bL[np][2 + sl]);
            }
    };

    load_stage(0, 0);
    if (NC > 1) load_stage(1, 1);

    for (int c = 0; c < NC; c++) {
        int s = c & 1;
        if (c + 1 < NC) asm volatile("cp.async.wait_group 1;" ::: "memory");
        else            asm volatile("cp.async.wait_group 0;" ::: "memory");
        __syncthreads();
        uint32_t st = sbase + s * STAGEB;

        uint32_t aH[4][4], aL[4][4], bH[2][4], bL[2][4];
        load_frags(st, 0, aH, aL, bH, bL);
        do_mma(aH, aL, bH, bL);

        load_frags(st, 1, aH, aL, bH, bL);
        __syncthreads();
        if (c + 2 < NC) load_stage(c + 2, s);
        do_mma(aH, aL, bH, bL);
    }

    // ---- epilogue ----
    #pragma unroll
    for (int mf = 0; mf < 4; mf++) {
        #pragma unroll
        for (int nf = 0; nf < 4; nf++) {
            int rA = row0 + wm * 64 + mf * 16 + (lane >> 2);
            int cB = col0 + wn * 32 + nf * 8 + (lane & 3) * 2;
            #pragma unroll
            for (int h = 0; h < 2; h++) {
                int rr = rA + h * 8;
                long long idx = (long long)rr * ldc + cB + zC;
                float v0 = acc[mf][nf][h * 2 + 0];
                float v1 = acc[mf][nf][h * 2 + 1];
                if (EPI == EF32) {
                    *(float2*)(Cf + idx) = make_float2(v0 * scale, v1 * scale);
                } else if (EPI == EQKVSA) {
                    if (col0 < 128) {
                        long long qi = (long long)rr * 128 + cB;
                        splitstore(Ch, Cl, qi,     v0 + bias[cB]);
                        splitstore(Ch, Cl, qi + 1, v1 + bias[cB + 1]);
                    } else {
                        long long vi = (long long)rr * 1024 + (cB - 128);
                        *(float2*)(Cf + vi) =
                            make_float2(v0 + bias[cB], v1 + bias[cB + 1]);
                    }
                } else if (EPI == ERELU2) {
                    float u0 = fmaxf(v0, 0.f), u1 = fmaxf(v1, 0.f);
                    splitstore(Ch, Cl, idx,     u0 * u0);
                    splitstore(Ch, Cl, idx + 1, u1 * u1);
                } else if (EPI == ERKV) {
                    splitstore(Ch, Cl, idx,
                               sigmoidf_(E1[idx]) * (v0 + bias[cB] + E0[idx]));
                    splitstore(Ch, Cl, idx + 1,
                               sigmoidf_(E1[idx + 1]) * (v1 + bias[cB + 1] + E0[idx + 1]));
                } else if (EPI == EADD) {
                    *(float2*)(Cf + idx) = make_float2(v0 + E0[idx], v1 + E0[idx + 1]);
                } else { // ECMFIN
                    float o0 = E0[idx]     + sigmoidf_(E1[idx])     * v0;
                    float o1 = E0[idx + 1] + sigmoidf_(E1[idx + 1]) * v1;
                    *(float2*)(Cf + idx) = make_float2(o0, o1);
                }
            }
        }
    }
}

// ---------------------------------------------------------------------------
// Weight prep: hi/lo fp16 planes + packing, one launch.
// Row pointers advance in FLOAT units (1024 floats per D-row).
// ---------------------------------------------------------------------------
__global__ __launch_bounds__(256)
void split_all_kernel(const float* tmv, const float* tmr, const float* qw,
                      const float* kw,  const float* svw, const float* ow,
                      const float* tow, const float* crw, const float* ckw,
                      const float* cvw,
                      const float* qb, const float* kb, const float* svb,
                      float* bias)
{
    const long long t0 = blockIdx.x * 256 + threadIdx.x;
    const long long st = (long long)gridDim.x * 256;
    const int DD4 = D_ * D_ / 4;

    if (blockIdx.x == 0)
        for (int t = threadIdx.x; t < 1152; t += 256)
            bias[t] = (t < 64) ? qb[t] : (t < 128) ? kb[t - 64] : svb[t - 128];

    for (long long i = t0; i < DD4; i += st)
        store_planes4(g_wvrh, g_wvrl, i * 4, ((const float4*)tmv)[i]);
    for (long long i = t0; i < DD4; i += st)
        store_planes4(g_wvrh + D_*D_, g_wvrl + D_*D_, i * 4, ((const float4*)tmr)[i]);
    for (long long i = t0; i < 1152 * 256; i += st) {
        int row = (int)(i >> 8), c = (int)(i & 255);
        const float* src = (row < 64)  ? qw  + (long long)row * 1024
                         : (row < 128) ? kw  + (long long)(row - 64) * 1024
                                       : svw + (long long)(row - 128) * 1024;
        store_planes4(g_wqksvh, g_wqksvl, i * 4, ((const float4*)src)[c]);
    }
    for (long long i = t0; i < DD4; i += st)
        store_planes4(g_woh,  g_wol,  i * 4, ((const float4*)ow)[i]);
    for (long long i = t0; i < DD4; i += st)
        store_planes4(g_wtoh, g_wtol, i * 4, ((const float4*)tow)[i]);
    for (long long i = t0; i < 5120 * 256; i += st) {
        int row = (int)(i >> 8), c = (int)(i & 255);
        const float* src = (row < 4096) ? ckw + (long long)row * 1024
                                        : crw + (long long)(row - 4096) * 1024;
        store_planes4(g_wckcrh, g_wckcrl, i * 4, ((const float4*)src)[c]);
    }
    for (long long i = t0; i < (long long)D_ * DI_ / 4; i += st)
        store_planes4(g_wcvh, g_wcvl, i * 4, ((const float4*)cvw)[i]);
}

// ---------------------------------------------------------------------------
// Fused RMSNorm + token-shift mix
// ---------------------------------------------------------------------------
__global__ __launch_bounds__(256)
void normmix_kernel(const float* __restrict__ x, const float* __restrict__ nw,
                    const float* __restrict__ mA, const float* __restrict__ mB,
                    fp16* __restrict__ x1h, fp16* __restrict__ x1l,
                    fp16* __restrict__ ah, fp16* __restrict__ al,
                    fp16* __restrict__ bh, fp16* __restrict__ bl)
{
    int n = blockIdx.x, tid = threadIdx.x;
    int prev = ((n & (S_ - 1)) == 0) ? n : n - 1;
    float4 xv = ((const float4*)(x + (long long)n    * D_))[tid];
    float4 pv = ((const float4*)(x + (long long)prev * D_))[tid];
    float ssn = xv.x*xv.x + xv.y*xv.y + xv.z*xv.z + xv.w*xv.w;
    float ssp = pv.x*pv.x + pv.y*pv.y + pv.z*pv.z + pv.w*pv.w;
    #pragma unroll
    for (int off = 16; off; off >>= 1) {
        ssn += __shfl_xor_sync(~0u, ssn, off);
        ssp += __shfl_xor_sync(~0u, ssp, off);
    }
    __shared__ float wn_[8], wp_[8];
    __shared__ float s_sn, s_sp;
    if ((tid & 31) == 0) { wn_[tid >> 5] = ssn; wp_[tid >> 5] = ssp; }
    __syncthreads();
    if (tid == 0) {
        float tn = 0.f, tp = 0.f;
        #pragma unroll
        for (int i = 0; i < 8; i++) { tn += wn_[i]; tp += wp_[i]; }
        s_sn = 1.f / (sqrtf(tn / (float)D_) + 1e-8f);
        s_sp = 1.f / (sqrtf(tp / (float)D_) + 1e-8f);
    }
    __syncthreads();
    float scn = s_sn, scp = s_sp;
    float4 wv = ((const float4*)nw)[tid];
    float4 xn = make_float4(xv.x*wv.x*scn, xv.y*wv.y*scn, xv.z*wv.z*scn, xv.w*wv.w*scn);
    float4 xp = make_float4(pv.x*wv.x*scp, pv.y*wv.y*scp, pv.z*wv.z*scp, pv.w*wv.w*scp);
    long long idx = (long long)n * D_ + tid * 4;
    if (x1h) store_planes4(x1h, x1l, idx, xn);
    float4 ma = ((const float4*)mA)[tid];
    float4 mb = ((const float4*)mB)[tid];
    float4 oa = make_float4(xn.x*ma.x + xp.x*(1.f-ma.x), xn.y*ma.y + xp.y*(1.f-ma.y),
                            xn.z*ma.z + xp.z*(1.f-ma.z), xn.w*ma.w + xp.w*(1.f-ma.w));
    float4 ob = make_float4(xn.x*mb.x + xp.x*(1.f-mb.x), xn.y*mb.y + xp.y*(1.f-mb.y),
                            xn.z*mb.z + xp.z*(1.f-mb.z), xn.w*mb.w + xp.w*(1.f-mb.w));
    store_planes4(ah, al, idx, oa);
    store_planes4(bh, bl, idx, ob);
}

// ---------------------------------------------------------------------------
// Top-k(32) + softmax + sparse V gather -> fp16 planes
// ---------------------------------------------------------------------------
__global__ __launch_bounds__(256)
void topk_attn_kernel(const float* __restrict__ scores, const float* __restrict__ V,
                      fp16* __restrict__ oh, fp16* __restrict__ ol)
{
    int q = blockIdx.x, b = q >> 12, qs = q & (S_ - 1), tid = threadIdx.x;
    const float* srow = scores + (long long)b * S_ * S_ + (long long)qs * S_;
    float s[16];
    #pragma unroll
    for (int i = 0; i < 16; i++) s[i] = srow[i * 256 + tid];

    __shared__ float wv[8]; __shared__ int wi[8];
    __shared__ float top_val[TOPK_]; __shared__ int top_idx[TOPK_];
    __shared__ int s_win;
    const float NEG = -__int_as_float(0x7f800000);

    for (int t = 0; t < TOPK_; t++) {
        float best = NEG; int bi = 0;
        #pragma unroll
        for (int i = 0; i < 16; i++) if (s[i] > best) { best = s[i]; bi = i; }
        int gidx = bi * 256 + tid;
        #pragma unroll
        for (int off = 16; off; off >>= 1) {
            float ov = __shfl_down_sync(~0u, best, off);
            int   oi = __shfl_down_sync(~0u, gidx, off);
            if (ov > best) { best = ov; gidx = oi; }
        }
        if ((tid & 31) == 0) { wv[tid >> 5] = best; wi[tid >> 5] = gidx; }
        __syncthreads();
        if (tid == 0) {
            float bb = wv[0]; int bbi = wi[0];
            #pragma unroll
            for (int w = 1; w < 8; w++) if (wv[w] > bb) { bb = wv[w]; bbi = wi[w]; }
            top_val[t] = bb; top_idx[t] = bbi; s_win = bbi;
        }
        __syncthreads();
        int win = s_win;
        if ((win & 255) == tid) s[win >> 8] = NEG;
    }

    __shared__ float wts[TOPK_];
    if (tid < 32) {
        float e = expf(top_val[tid] - top_val[0]);
        float ssum = e;
        #pragma unroll
        for (int off = 16; off; off >>= 1) ssum += __shfl_xor_sync(~0u, ssum, off);
        wts[tid] = e / ssum;
    }
    __syncthreads();

    const float* Vb = V + (long long)b * S_ * D_;
    float4 acc = make_float4(0.f, 0.f, 0.f, 0.f);
    #pragma unroll
    for (int t = 0; t < TOPK_; t++) {
        float w = wts[t];
        float4 vr = *(const float4*)&Vb[(long long)top_idx[t] * D_ + tid * 4];
        acc.x += w*vr.x; acc.y += w*vr.y; acc.z += w*vr.z; acc.w += w*vr.w;
    }
    store_planes4(oh, ol, (long long)q * D_ + tid * 4, acc);
}

// ---------------------------------------------------------------------------
// Host
// ---------------------------------------------------------------------------
template <typename T> static void* symaddr(T& sym)
{ void* p = nullptr; cudaGetSymbolAddress(&p, sym); return p; }

extern "C" void kernel_launch(void* const* d_in, const int* in_sizes, int n_in,
                              void* d_out, int out_size)
{
    const float* x        = (const float*)d_in[0];
    const float* norm1_w  = (const float*)d_in[1];
    const float* tm_mix_v = (const float*)d_in[3];
    const float* tm_mix_r = (const float*)d_in[4];
    const float* tm_value_w  = (const float*)d_in[6];
    const float* tm_recept_w = (const float*)d_in[7];
    const float* tm_out_w = (const float*)d_in[8];
    const float* sa_q_w   = (const float*)d_in[9];
    const float* sa_q_b   = (const float*)d_in[10];
    const float* sa_k_w   = (const float*)d_in[11];
    const float* sa_k_b   = (const float*)d_in[12];
    const float* sa_v_w   = (const float*)d_in[13];
    const float* sa_v_b   = (const float*)d_in[14];
    const float* sa_o_w   = (const float*)d_in[15];
    const float* sa_o_b   = (const float*)d_in[16];
    const float* norm2_w  = (const float*)d_in[17];
    const float* cm_mix_k = (const float*)d_in[18];
    const float* cm_mix_r = (const float*)d_in[19];
    const float* cm_key_w = (const float*)d_in[20];
    const float* cm_recept_w = (const float*)d_in[21];
    const float* cm_value_w  = (const float*)d_in[22];
    float* out = (float*)d_out;

    float* vr   = (float*)symaddr(g_vr);
    float* Vsa  = (float*)symaddr(g_Vsa);
    float* sc   = (float*)symaddr(g_scores);
    float* xmid = (float*)symaddr(g_xmid);
    float* r2   = (float*)symaddr(g_r2);
    float* bias = (float*)symaddr(g_bias);

    fp16 *x1h=(fp16*)symaddr(g_x1h),   *x1l=(fp16*)symaddr(g_x1l);
    fp16 *xabh=(fp16*)symaddr(g_xabh), *xabl=(fp16*)symaddr(g_xabl);
    fp16 *qkh=(fp16*)symaddr(g_qkh),   *qkl=(fp16*)symaddr(g_qkl);
    fp16 *aph=(fp16*)symaddr(g_aph),   *apl=(fp16*)symaddr(g_apl);
    fp16 *rkh=(fp16*)symaddr(g_rkh),   *rkl=(fp16*)symaddr(g_rkl);
    fp16 *kch=(fp16*)symaddr(g_kch),   *kcl=(fp16*)symaddr(g_kcl);
    fp16 *wvrh=(fp16*)symaddr(g_wvrh),     *wvrl=(fp16*)symaddr(g_wvrl);
    fp16 *wqksvh=(fp16*)symaddr(g_wqksvh), *wqksvl=(fp16*)symaddr(g_wqksvl);
    fp16 *woh=(fp16*)symaddr(g_woh),   *wol=(fp16*)symaddr(g_wol);
    fp16 *wtoh=(fp16*)symaddr(g_wtoh), *wtol=(fp16*)symaddr(g_wtol);
    fp16 *wckcrh=(fp16*)symaddr(g_wckcrh), *wckcrl=(fp16*)symaddr(g_wckcrl);
    fp16 *wcvh=(fp16*)symaddr(g_wcvh), *wcvl=(fp16*)symaddr(g_wcvl);

    const int SMB = 2 * STAGEB;   // 81920 -> 2 CTAs/SM
    cudaFuncSetAttribute(gemm_mma<EF32>,   cudaFuncAttributeMaxDynamicSharedMemorySize, SMB);
    cudaFuncSetAttribute(gemm_mma<EQKVSA>, cudaFuncAttributeMaxDynamicSharedMemorySize, SMB);
    cudaFuncSetAttribute(gemm_mma<ERKV>,   cudaFuncAttributeMaxDynamicSharedMemorySize, SMB);
    cudaFuncSetAttribute(gemm_mma<EADD>,   cudaFuncAttributeMaxDynamicSharedMemorySize, SMB);
    cudaFuncSetAttribute(gemm_mma<ERELU2>, cudaFuncAttributeMaxDynamicSharedMemorySize, SMB);
    cudaFuncSetAttribute(gemm_mma<ECMFIN>, cudaFuncAttributeMaxDynamicSharedMemorySize, SMB);

    // 0: weight prep (hi/lo planes + packing)
    split_all_kernel<<<2048, 256>>>(tm_value_w, tm_recept_w, sa_q_w, sa_k_w,
                                    sa_v_w, sa_o_w, tm_out_w, cm_recept_w,
                                    cm_key_w, cm_value_w,
                                    sa_q_b, sa_k_b, sa_v_b, bias);

    // 1: fused norm1 + mix1 (emits x1 planes + xa/xb planes)
    normmix_kernel<<<N_, 256>>>(x, norm1_w, tm_mix_v, tm_mix_r,
                                x1h, x1l,
                                xabh, xabl, xabh + (long long)N_*D_, xabl + (long long)N_*D_);

    // 2: merged QK + Vsa projection
    gemm_mma<EQKVSA><<<dim3(9,64,1), 256, SMB>>>(x1h, x1l, D_, wqksvh, wqksvl, D_,
        bias, nullptr, nullptr, Vsa, qkh, qkl, 1152, D_, 1.f, 0, 0, 0);

    // 3: batched v,r
    gemm_mma<EF32><<<dim3(8,64,2), 256, SMB>>>(xabh, xabl, D_, wvrh, wvrl, D_,
        nullptr, nullptr, nullptr, vr, nullptr, nullptr, D_, D_, 1.f,
        (long long)N_*D_, (long long)D_*D_, (long long)N_*D_);

    // 4: scores = Q @ K^T / 8
    gemm_mma<EF32><<<dim3(32,32,2), 256, SMB>>>(qkh, qkl, 128, qkh + 64, qkl + 64, 128,
        nullptr, nullptr, nullptr, sc, nullptr, nullptr, S_, 64, 0.125f,
        (long long)S_*128, (long long)S_*128, (long long)S_*S_);

    // 5: topk + softmax + gather
    topk_attn_kernel<<<N_, 256>>>(sc, Vsa, aph, apl);

    // 6: rkv = sigmoid(r)*(ap@o_w^T + o_b + v)
    gemm_mma<ERKV><<<dim3(8,64,1), 256, SMB>>>(aph, apl, D_, woh, wol, D_,
        sa_o_b, vr, vr + (long long)N_*D_, nullptr, rkh, rkl, D_, D_, 1.f, 0, 0, 0);
    // 7: xmid = x + rkv@tm_out^T
    gemm_mma<EADD><<<dim3(8,64,1), 256, SMB>>>(rkh, rkl, D_, wtoh, wtol, D_,
        nullptr, x, nullptr, xmid, nullptr, nullptr, D_, D_, 1.f, 0, 0, 0);

    // 8: fused norm2 + mix2 (no x planes needed)
    normmix_kernel<<<N_, 256>>>(xmid, norm2_w, cm_mix_k, cm_mix_r,
                                nullptr, nullptr,
                                xabh, xabl, xabh + (long long)N_*D_, xabl + (long long)N_*D_);

    // 9a: kc = relu(xa@ck^T)^2  (plane output)
    gemm_mma<ERELU2><<<dim3(32,64,1), 256, SMB>>>(xabh, xabl, D_, wckcrh, wckcrl, D_,
        nullptr, nullptr, nullptr, nullptr, kch, kcl, DI_, D_, 1.f, 0, 0, 0);
    // 9b: r2 = xb@cr^T  (plain f32 output)
    gemm_mma<EF32><<<dim3(8,64,1), 256, SMB>>>(
        xabh + (long long)N_*D_, xabl + (long long)N_*D_, D_,
        wckcrh + (long long)4096*D_, wckcrl + (long long)4096*D_, D_,
        nullptr, nullptr, nullptr, r2, nullptr, nullptr, 1024, D_, 1.f, 0, 0, 0);

    // 10: out = xmid + sigmoid(r2)*(kc@cv^T)
    gemm_mma<ECMFIN><<<dim3(8,64,1), 256, SMB>>>(kch, kcl, DI_, wcvh, wcvl, DI_,
        nullptr, xmid, r2, out, nullptr, nullptr, D_, DI_, 1.f, 0, 0, 0);
}

// round 15
// speedup vs baseline: 2.5052x; 1.0722x over previous
#include <cuda_runtime.h>
#include <cuda_fp16.h>
#include <math.h>
#include <stdint.h>

#define D_    1024
#define A_    64
#define TOPK_ 32
#define B_    2
#define S_    4096
#define N_    (B_ * S_)
#define DI_   4096

typedef __half fp16;

// ---------------------------------------------------------------------------
// Device-global scratch
// ---------------------------------------------------------------------------
__device__ __align__(256) float g_vr[2 * N_ * D_];          // v then r
__device__ __align__(256) float g_Vsa[N_ * D_];
__device__ __align__(256) float g_scores[(long long)B_ * S_ * S_];
__device__ __align__(256) float g_xmid[N_ * D_];
__device__ __align__(256) float g_r2[N_ * D_];
__device__ __align__(256) float g_bias[1152];

__device__ __align__(256) fp16 g_x1h[N_ * D_],  g_x1l[N_ * D_];
__device__ __align__(256) fp16 g_xabh[2 * N_ * D_], g_xabl[2 * N_ * D_];   // xa | xb
__device__ __align__(256) fp16 g_qkh[N_ * 128], g_qkl[N_ * 128];
__device__ __align__(256) fp16 g_aph[N_ * D_],  g_apl[N_ * D_];
__device__ __align__(256) fp16 g_rkh[N_ * D_],  g_rkl[N_ * D_];
__device__ __align__(256) fp16 g_kch[(long long)N_ * DI_], g_kcl[(long long)N_ * DI_];

// hi/lo fp16 weights
__device__ __align__(256) fp16 g_wvrh[2 * D_ * D_],  g_wvrl[2 * D_ * D_];
__device__ __align__(256) fp16 g_wqksvh[1152 * D_],  g_wqksvl[1152 * D_];
__device__ __align__(256) fp16 g_woh[D_ * D_],   g_wol[D_ * D_];
__device__ __align__(256) fp16 g_wtoh[D_ * D_],  g_wtol[D_ * D_];
__device__ __align__(256) fp16 g_wckcrh[5120 * D_], g_wckcrl[5120 * D_];   // [ck;cr]
__device__ __align__(256) fp16 g_wcvh[(long long)D_ * DI_], g_wcvl[(long long)D_ * DI_];

// ---------------------------------------------------------------------------
// Helpers
// ---------------------------------------------------------------------------
__device__ __forceinline__ float sigmoidf_(float x) { return 1.f / (1.f + expf(-x)); }

__device__ __forceinline__ void splitstore2(fp16* H, fp16* L, long long idx,
                                            float v0, float v1)
{
    __half2 h = __floats2half2_rn(v0, v1);
    float h0 = __half2float(__low2half(h)), h1 = __half2float(__high2half(h));
    __half2 l = __floats2half2_rn(v0 - h0, v1 - h1);
    *(__half2*)(H + idx) = h;
    *(__half2*)(L + idx) = l;
}

__device__ __forceinline__ void store_planes4(fp16* H, fp16* L, long long idx, float4 v)
{
    __half2 h01 = __floats2half2_rn(v.x, v.y);
    __half2 h23 = __floats2half2_rn(v.z, v.w);
    float h0f = __half2float(__low2half(h01)),  h1f = __half2float(__high2half(h01));
    float h2f = __half2float(__low2half(h23)),  h3f = __half2float(__high2half(h23));
    __half2 l01 = __floats2half2_rn(v.x - h0f, v.y - h1f);
    __half2 l23 = __floats2half2_rn(v.z - h2f, v.w - h3f);
    ((__half2*)(H + idx))[0] = h01; ((__half2*)(H + idx))[1] = h23;
    ((__half2*)(L + idx))[0] = l01; ((__half2*)(L + idx))[1] = l23;
}

__device__ __forceinline__ uint32_t smem_u32(const void* p)
{
    uint32_t a;
    asm("{ .reg .u64 t; cvta.to.shared.u64 t, %1; cvt.u32.u64 %0, t; }" : "=r"(a) : "l"(p));
    return a;
}
__device__ __forceinline__ void cp16(uint32_t s, const void* g)
{
    asm volatile("cp.async.cg.shared.global [%0], [%1], 16;" :: "r"(s), "l"(g));
}
__device__ __forceinline__ void ldsm4(uint32_t* r, uint32_t addr)
{
    asm volatile("ldmatrix.sync.aligned.m8n8.x4.shared.b16 {%0,%1,%2,%3}, [%4];"
                 : "=r"(r[0]), "=r"(r[1]), "=r"(r[2]), "=r"(r[3]) : "r"(addr));
}
__device__ __forceinline__ void mma16816(float* c, const uint32_t* a,
                                         uint32_t b0, uint32_t b1)
{
    asm volatile(
        "mma.sync.aligned.m16n8k16.row.col.f32.f16.f16.f32 "
        "{%0,%1,%2,%3},{%4,%5,%6,%7},{%8,%9},{%0,%1,%2,%3};"
        : "+f"(c[0]), "+f"(c[1]), "+f"(c[2]), "+f"(c[3])
        : "r"(a[0]), "r"(a[1]), "r"(a[2]), "r"(a[3]), "r"(b0), "r"(b1));
}

#define EF32    0
#define ERKV    3   /* planes, sigmoid(E1)*(acc+bias+E0)  */
#define EADD    4   /* f32, acc+E0                        */
#define ECMFIN  5   /* f32, E0 + sigmoid(E1)*acc          */
#define EMEGA1  7   /* z=0: qk planes + Vsa; z=1,2: v,r into Cf2 */
#define EMEGA2  8   /* z<4: kc relu^2 planes; z=4: r2 f32 */

// ---------------------------------------------------------------------------
// fp16 split NT GEMM on mma.sync, 3-pass: C = Ah*Bh + Al*Bh + Ah*Bl
// (omitted Al*Bl ~2^-24). fp32 accum. CTA 128x128, BK=32, 2-stage cp.async.
// EMEGA variants pack multiple independent GEMM jobs via blockIdx.z remap.
// ---------------------------------------------------------------------------
#define ROWB   80
#define PLANE  (128 * ROWB)        /* 10240 B */
#define STAGEB (4 * PLANE)         /* 40960 B */

template<int EPI>
__global__ __launch_bounds__(256, 2)
void gemm_mma(const fp16* __restrict__ Ah, const fp16* __restrict__ Al, int lda,
              const fp16* __restrict__ Bh, const fp16* __restrict__ Bl, int ldb,
              const float* __restrict__ bias, const float* __restrict__ E0,
              const float* __restrict__ E1,
              float* __restrict__ Cf, fp16* __restrict__ Ch, fp16* __restrict__ Cl,
              int ldc, int K, float scale,
              long long sA, long long sB, long long sC,
              const fp16* __restrict__ A2h, const fp16* __restrict__ A2l,
              const fp16* __restrict__ B2h, const fp16* __restrict__ B2l,
              float* __restrict__ Cf2)
{
    extern __shared__ __align__(256) char smem[];

    // ---- job remap ----
    if (EPI == EMEGA1) {
        int z = blockIdx.z;
        if (z > 0) {
            if (blockIdx.x == 8) return;     // qk column block exists only for z=0
            Ah = A2h + (long long)(z - 1) * sA;
            Al = A2l + (long long)(z - 1) * sA;
            Bh = B2h + (long long)(z - 1) * sB;
            Bl = B2l + (long long)(z - 1) * sB;
        }
    } else if (EPI == EMEGA2) {
        int z = blockIdx.z;
        if (z < 4) {
            Bh += (long long)z * 1024 * D_;
            Bl += (long long)z * 1024 * D_;
        } else {
            Ah = A2h; Al = A2l;
            Bh += (long long)4096 * D_;
            Bl += (long long)4096 * D_;
        }
    } else {
        Ah += (long long)blockIdx.z * sA;  Al += (long long)blockIdx.z * sA;
        Bh += (long long)blockIdx.z * sB;  Bl += (long long)blockIdx.z * sB;
    }
    const long long zC = (EPI == EMEGA1 || EPI == EMEGA2)
                       ? 0 : (long long)blockIdx.z * sC;

    const int tid  = threadIdx.x;
    const int lane = tid & 31;
    const int wid  = tid >> 5;
    const int wm   = wid & 1;
    const int wn   = wid >> 1;
    const int row0 = blockIdx.y * 128;
    const int col0 = blockIdx.x * 128;

    const uint32_t sbase = smem_u32(smem);
    const int NC = K >> 5;

    float acc[4][4][4];
    #pragma unroll
    for (int mf = 0; mf < 4; mf++)
        #pragma unroll
        for (int nf = 0; nf < 4; nf++)
            #pragma unroll
            for (int e = 0; e < 4; e++) acc[mf][nf][e] = 0.f;

    auto load_stage = [&](int c, int s) {
        uint32_t st = sbase + s * STAGEB;
        int k0 = c << 5;
        const fp16* srcs[4] = { Ah, Al, Bh, Bl };
        #pragma unroll
        for (int p = 0; p < 4; p++) {
            int base = (p < 2) ? row0 : col0;
            int ld   = (p < 2) ? lda : ldb;
            const fp16* sp = srcs[p] + (long long)base * ld + k0;
            uint32_t db = st + p * PLANE;
            #pragma unroll
            for (int i = tid; i < 512; i += 256) {
                int rr = i >> 2, ch = i & 3;
                cp16(db + rr * ROWB + ch * 16, sp + (long long)rr * ld + ch * 8);
            }
        }
        asm volatile("cp.async.commit_group;" ::: "memory");
    };

    auto load_frags = [&](uint32_t st, int kk,
                          uint32_t (&aH)[4][4], uint32_t (&aL)[4][4],
                          uint32_t (&bH)[2][4], uint32_t (&bL)[2][4]) {
        int chunk = (kk * 2 + (lane >> 4)) * 16;
        int arow  = wm * 64 + (lane & 15);
        #pragma unroll
        for (int mf = 0; mf < 4; mf++) {
            uint32_t off = (uint32_t)(arow + mf * 16) * ROWB + chunk;
            ldsm4(aH[mf], st + off);
            ldsm4(aL[mf], st + PLANE + off);
        }
        int brow = wn * 32 + (lane & 7) + ((lane >> 3) & 1) * 8;
        #pragma unroll
        for (int np = 0; np < 2; np++) {
            uint32_t off = (uint32_t)(brow + np * 16) * ROWB + chunk;
            ldsm4(bH[np], st + 2 * PLANE + off);
            ldsm4(bL[np], st + 3 * PLANE + off);
        }
    };

    auto do_mma = [&](uint32_t (&aH)[4][4], uint32_t (&aL)[4][4],
                      uint32_t (&bH)[2][4], uint32_t (&bL)[2][4]) {
        #pragma unroll
        for (int mf = 0; mf < 4; mf++)
            #pragma unroll
            for (int nf = 0; nf < 4; nf++) {
                int np = nf >> 1, sl = nf & 1;
                mma16816(acc[mf][nf], aH[mf], bH[np][sl], bH[np][2 + sl]);
            }
        #pragma unroll
        for (int mf = 0; mf < 4; mf++)
            #pragma unroll
            for (int nf = 0; nf < 4; nf++) {
                int np = nf >> 1, sl = nf & 1;
                mma16816(acc[mf][nf], aL[mf], bH[np][sl], bH[np][2 + sl]);
            }
        #pragma unroll
        for (int mf = 0; mf < 4; mf++)
            #pragma unroll
            for (int nf = 0; nf < 4; nf++) {
                int np = nf >> 1, sl = nf & 1;
                mma16816(acc[mf][nf], aH[mf], bL[np][sl], bL[np][2 + sl]);
            }
    };

    load_stage(0, 0);
    if (NC > 1) load_stage(1, 1);

    for (int c = 0; c < NC; c++) {
        int s = c & 1;
        if (c + 1 < NC) asm volatile("cp.async.wait_group 1;" ::: "memory");
        else            asm volatile("cp.async.wait_group 0;" ::: "memory");
        __syncthreads();
        uint32_t st = sbase + s * STAGEB;

        uint32_t aH[4][4], aL[4][4], bH[2][4], bL[2][4];
        load_frags(st, 0, aH, aL, bH, bL);
        do_mma(aH, aL, bH, bL);

        load_frags(st, 1, aH, aL, bH, bL);
        __syncthreads();
        if (c + 2 < NC) load_stage(c + 2, s);
        do_mma(aH, aL, bH, bL);
    }

    // ---- epilogue ----
    #pragma unroll
    for (int mf = 0; mf < 4; mf++) {
        #pragma unroll
        for (int nf = 0; nf < 4; nf++) {
            int rA = row0 + wm * 64 + mf * 16 + (lane >> 2);
            int cB = col0 + wn * 32 + nf * 8 + (lane & 3) * 2;
            #pragma unroll
            for (int h = 0; h < 2; h++) {
                int rr = rA + h * 8;
                long long idx = (long long)rr * ldc + cB + zC;
                float v0 = acc[mf][nf][h * 2 + 0];
                float v1 = acc[mf][nf][h * 2 + 1];
                if (EPI == EF32) {
                    *(float2*)(Cf + idx) = make_float2(v0 * scale, v1 * scale);
                } else if (EPI == EMEGA1) {
                    if (blockIdx.z == 0) {
                        if (col0 < 128) {
                            long long qi = (long long)rr * 128 + cB;
                            splitstore2(Ch, Cl, qi, v0 + bias[cB], v1 + bias[cB + 1]);
                        } else {
                            long long vi = (long long)rr * 1024 + (cB - 128);
                            *(float2*)(Cf + vi) =
                                make_float2(v0 + bias[cB], v1 + bias[cB + 1]);
                        }
                    } else {
                        long long o = (long long)(blockIdx.z - 1) * ((long long)N_ * D_)
                                    + (long long)rr * 1024 + cB;
                        *(float2*)(Cf2 + o) = make_float2(v0, v1);
                    }
                } else if (EPI == EMEGA2) {
                    if (blockIdx.z < 4) {
                        long long ki = (long long)rr * 4096
                                     + (long long)blockIdx.z * 1024 + cB;
                        float u0 = fmaxf(v0, 0.f), u1 = fmaxf(v1, 0.f);
                        splitstore2(Ch, Cl, ki, u0 * u0, u1 * u1);
                    } else {
                        *(float2*)(Cf + (long long)rr * 1024 + cB) =
                            make_float2(v0, v1);
                    }
                } else if (EPI == ERKV) {
                    float o0 = sigmoidf_(E1[idx]) * (v0 + bias[cB] + E0[idx]);
                    float o1 = sigmoidf_(E1[idx + 1]) * (v1 + bias[cB + 1] + E0[idx + 1]);
                    splitstore2(Ch, Cl, idx, o0, o1);
                } else if (EPI == EADD) {
                    *(float2*)(Cf + idx) = make_float2(v0 + E0[idx], v1 + E0[idx + 1]);
                } else { // ECMFIN
                    float o0 = E0[idx]     + sigmoidf_(E1[idx])     * v0;
                    float o1 = E0[idx + 1] + sigmoidf_(E1[idx + 1]) * v1;
                    *(float2*)(Cf + idx) = make_float2(o0, o1);
                }
            }
        }
    }
}

// ---------------------------------------------------------------------------
// Weight prep: hi/lo fp16 planes + packing, one launch.
// Row pointers advance in FLOAT units (1024 floats per D-row).
// ---------------------------------------------------------------------------
__global__ __launch_bounds__(256)
void split_all_kernel(const float* tmv, const float* tmr, const float* qw,
                      const float* kw,  const float* svw, const float* ow,
                      const float* tow, const float* crw, const float* ckw,
                      const float* cvw,
                      const float* qb, const float* kb, const float* svb,
                      float* bias)
{
    const long long t0 = blockIdx.x * 256 + threadIdx.x;
    const long long st = (long long)gridDim.x * 256;
    const int DD4 = D_ * D_ / 4;

    if (blockIdx.x == 0)
        for (int t = threadIdx.x; t < 1152; t += 256)
            bias[t] = (t < 64) ? qb[t] : (t < 128) ? kb[t - 64] : svb[t - 128];

    for (long long i = t0; i < DD4; i += st)
        store_planes4(g_wvrh, g_wvrl, i * 4, ((const float4*)tmv)[i]);
    for (long long i = t0; i < DD4; i += st)
        store_planes4(g_wvrh + D_*D_, g_wvrl + D_*D_, i * 4, ((const float4*)tmr)[i]);
    for (long long i = t0; i < 1152 * 256; i += st) {
        int row = (int)(i >> 8), c = (int)(i & 255);
        const float* src = (row < 64)  ? qw  + (long long)row * 1024
                         : (row < 128) ? kw  + (long long)(row - 64) * 1024
                                       : svw + (long long)(row - 128) * 1024;
        store_planes4(g_wqksvh, g_wqksvl, i * 4, ((const float4*)src)[c]);
    }
    for (long long i = t0; i < DD4; i += st)
        store_planes4(g_woh,  g_wol,  i * 4, ((const float4*)ow)[i]);
    for (long long i = t0; i < DD4; i += st)
        store_planes4(g_wtoh, g_wtol, i * 4, ((const float4*)tow)[i]);
    for (long long i = t0; i < 5120 * 256; i += st) {
        int row = (int)(i >> 8), c = (int)(i & 255);
        const float* src = (row < 4096) ? ckw + (long long)row * 1024
                                        : crw + (long long)(row - 4096) * 1024;
        store_planes4(g_wckcrh, g_wckcrl, i * 4, ((const float4*)src)[c]);
    }
    for (long long i = t0; i < (long long)D_ * DI_ / 4; i += st)
        store_planes4(g_wcvh, g_wcvl, i * 4, ((const float4*)cvw)[i]);
}

// ---------------------------------------------------------------------------
// Fused RMSNorm + token-shift mix
// ---------------------------------------------------------------------------
__global__ __launch_bounds__(256)
void normmix_kernel(const float* __restrict__ x, const float* __restrict__ nw,
                    const float* __restrict__ mA, const float* __restrict__ mB,
                    fp16* __restrict__ x1h, fp16* __restrict__ x1l,
                    fp16* __restrict__ ah, fp16* __restrict__ al,
                    fp16* __restrict__ bh, fp16* __restrict__ bl)
{
    int n = blockIdx.x, tid = threadIdx.x;
    int prev = ((n & (S_ - 1)) == 0) ? n : n - 1;
    float4 xv = ((const float4*)(x + (long long)n    * D_))[tid];
    float4 pv = ((const float4*)(x + (long long)prev * D_))[tid];
    float ssn = xv.x*xv.x + xv.y*xv.y + xv.z*xv.z + xv.w*xv.w;
    float ssp = pv.x*pv.x + pv.y*pv.y + pv.z*pv.z + pv.w*pv.w;
    #pragma unroll
    for (int off = 16; off; off >>= 1) {
        ssn += __shfl_xor_sync(~0u, ssn, off);
        ssp += __shfl_xor_sync(~0u, ssp, off);
    }
    __shared__ float wn_[8], wp_[8];
    __shared__ float s_sn, s_sp;
    if ((tid & 31) == 0) { wn_[tid >> 5] = ssn; wp_[tid >> 5] = ssp; }
    __syncthreads();
    if (tid == 0) {
        float tn = 0.f, tp = 0.f;
        #pragma unroll
        for (int i = 0; i < 8; i++) { tn += wn_[i]; tp += wp_[i]; }
        s_sn = 1.f / (sqrtf(tn / (float)D_) + 1e-8f);
        s_sp = 1.f / (sqrtf(tp / (float)D_) + 1e-8f);
    }
    __syncthreads();
    float scn = s_sn, scp = s_sp;
    float4 wv = ((const float4*)nw)[tid];
    float4 xn = make_float4(xv.x*wv.x*scn, xv.y*wv.y*scn, xv.z*wv.z*scn, xv.w*wv.w*scn);
    float4 xp = make_float4(pv.x*wv.x*scp, pv.y*wv.y*scp, pv.z*wv.z*scp, pv.w*wv.w*scp);
    long long idx = (long long)n * D_ + tid * 4;
    if (x1h) store_planes4(x1h, x1l, idx, xn);
    float4 ma = ((const float4*)mA)[tid];
    float4 mb = ((const float4*)mB)[tid];
    float4 oa = make_float4(xn.x*ma.x + xp.x*(1.f-ma.x), xn.y*ma.y + xp.y*(1.f-ma.y),
                            xn.z*ma.z + xp.z*(1.f-ma.z), xn.w*ma.w + xp.w*(1.f-ma.w));
    float4 ob = make_float4(xn.x*mb.x + xp.x*(1.f-mb.x), xn.y*mb.y + xp.y*(1.f-mb.y),
                            xn.z*mb.z + xp.z*(1.f-mb.z), xn.w*mb.w + xp.w*(1.f-mb.w));
    store_planes4(ah, al, idx, oa);
    store_planes4(bh, bl, idx, ob);
}

// ---------------------------------------------------------------------------
// Top-k(32) + softmax + sparse V gather -> fp16 planes
// ---------------------------------------------------------------------------
__global__ __launch_bounds__(256)
void topk_attn_kernel(const float* __restrict__ scores, const float* __restrict__ V,
                      fp16* __restrict__ oh, fp16* __restrict__ ol)
{
    int q = blockIdx.x, b = q >> 12, qs = q & (S_ - 1), tid = threadIdx.x;
    const float* srow = scores + (long long)b * S_ * S_ + (long long)qs * S_;
    float s[16];
    #pragma unroll
    for (int i = 0; i < 16; i++) s[i] = srow[i * 256 + tid];

    __shared__ float wv[8]; __shared__ int wi[8];
    __shared__ float top_val[TOPK_]; __shared__ int top_idx[TOPK_];
    __shared__ int s_win;
    const float NEG = -__int_as_float(0x7f800000);

    for (int t = 0; t < TOPK_; t++) {
        float best = NEG; int bi = 0;
        #pragma unroll
        for (int i = 0; i < 16; i++) if (s[i] > best) { best = s[i]; bi = i; }
        int gidx = bi * 256 + tid;
        #pragma unroll
        for (int off = 16; off; off >>= 1) {
            float ov = __shfl_down_sync(~0u, best, off);
            int   oi = __shfl_down_sync(~0u, gidx, off);
            if (ov > best) { best = ov; gidx = oi; }
        }
        if ((tid & 31) == 0) { wv[tid >> 5] = best; wi[tid >> 5] = gidx; }
        __syncthreads();
        if (tid == 0) {
            float bb = wv[0]; int bbi = wi[0];
            #pragma unroll
            for (int w = 1; w < 8; w++) if (wv[w] > bb) { bb = wv[w]; bbi = wi[w]; }
            top_val[t] = bb; top_idx[t] = bbi; s_win = bbi;
        }
        __syncthreads();
        int win = s_win;
        if ((win & 255) == tid) s[win >> 8] = NEG;
    }

    __shared__ float wts[TOPK_];
    if (tid < 32) {
        float e = expf(top_val[tid] - top_val[0]);
        float ssum = e;
        #pragma unroll
        for (int off = 16; off; off >>= 1) ssum += __shfl_xor_sync(~0u, ssum, off);
        wts[tid] = e / ssum;
    }
    __syncthreads();

    const float* Vb = V + (long long)b * S_ * D_;
    float4 acc = make_float4(0.f, 0.f, 0.f, 0.f);
    #pragma unroll
    for (int t = 0; t < TOPK_; t++) {
        float w = wts[t];
        float4 vr = *(const float4*)&Vb[(long long)top_idx[t] * D_ + tid * 4];
        acc.x += w*vr.x; acc.y += w*vr.y; acc.z += w*vr.z; acc.w += w*vr.w;
    }
    store_planes4(oh, ol, (long long)q * D_ + tid * 4, acc);
}

// ---------------------------------------------------------------------------
// Host
// ---------------------------------------------------------------------------
template <typename T> static void* symaddr(T& sym)
{ void* p = nullptr; cudaGetSymbolAddress(&p, sym); return p; }

extern "C" void kernel_launch(void* const* d_in, const int* in_sizes, int n_in,
                              void* d_out, int out_size)
{
    const float* x        = (const float*)d_in[0];
    const float* norm1_w  = (const float*)d_in[1];
    const float* tm_mix_v = (const float*)d_in[3];
    const float* tm_mix_r = (const float*)d_in[4];
    const float* tm_value_w  = (const float*)d_in[6];
    const float* tm_recept_w = (const float*)d_in[7];
    const float* tm_out_w = (const float*)d_in[8];
    const float* sa_q_w   = (const float*)d_in[9];
    const float* sa_q_b   = (const float*)d_in[10];
    const float* sa_k_w   = (const float*)d_in[11];
    const float* sa_k_b   = (const float*)d_in[12];
    const float* sa_v_w   = (const float*)d_in[13];
    const float* sa_v_b   = (const float*)d_in[14];
    const float* sa_o_w   = (const float*)d_in[15];
    const float* sa_o_b   = (const float*)d_in[16];
    const float* norm2_w  = (const float*)d_in[17];
    const float* cm_mix_k = (const float*)d_in[18];
    const float* cm_mix_r = (const float*)d_in[19];
    const float* cm_key_w = (const float*)d_in[20];
    const float* cm_recept_w = (const float*)d_in[21];
    const float* cm_value_w  = (const float*)d_in[22];
    float* out = (float*)d_out;

    float* vr   = (float*)symaddr(g_vr);
    float* Vsa  = (float*)symaddr(g_Vsa);
    float* sc   = (float*)symaddr(g_scores);
    float* xmid = (float*)symaddr(g_xmid);
    float* r2   = (float*)symaddr(g_r2);
    float* bias = (float*)symaddr(g_bias);

    fp16 *x1h=(fp16*)symaddr(g_x1h),   *x1l=(fp16*)symaddr(g_x1l);
    fp16 *xabh=(fp16*)symaddr(g_xabh), *xabl=(fp16*)symaddr(g_xabl);
    fp16 *qkh=(fp16*)symaddr(g_qkh),   *qkl=(fp16*)symaddr(g_qkl);
    fp16 *aph=(fp16*)symaddr(g_aph),   *apl=(fp16*)symaddr(g_apl);
    fp16 *rkh=(fp16*)symaddr(g_rkh),   *rkl=(fp16*)symaddr(g_rkl);
    fp16 *kch=(fp16*)symaddr(g_kch),   *kcl=(fp16*)symaddr(g_kcl);
    fp16 *wvrh=(fp16*)symaddr(g_wvrh),     *wvrl=(fp16*)symaddr(g_wvrl);
    fp16 *wqksvh=(fp16*)symaddr(g_wqksvh), *wqksvl=(fp16*)symaddr(g_wqksvl);
    fp16 *woh=(fp16*)symaddr(g_woh),   *wol=(fp16*)symaddr(g_wol);
    fp16 *wtoh=(fp16*)symaddr(g_wtoh), *wtol=(fp16*)symaddr(g_wtol);
    fp16 *wckcrh=(fp16*)symaddr(g_wckcrh), *wckcrl=(fp16*)symaddr(g_wckcrl);
    fp16 *wcvh=(fp16*)symaddr(g_wcvh), *wcvl=(fp16*)symaddr(g_wcvl);

    const int SMB = 2 * STAGEB;   // 81920 -> 2 CTAs/SM
    cudaFuncSetAttribute(gemm_mma<EF32>,   cudaFuncAttributeMaxDynamicSharedMemorySize, SMB);
    cudaFuncSetAttribute(gemm_mma<ERKV>,   cudaFuncAttributeMaxDynamicSharedMemorySize, SMB);
    cudaFuncSetAttribute(gemm_mma<EADD>,   cudaFuncAttributeMaxDynamicSharedMemorySize, SMB);
    cudaFuncSetAttribute(gemm_mma<ECMFIN>, cudaFuncAttributeMaxDynamicSharedMemorySize, SMB);
    cudaFuncSetAttribute(gemm_mma<EMEGA1>, cudaFuncAttributeMaxDynamicSharedMemorySize, SMB);
    cudaFuncSetAttribute(gemm_mma<EMEGA2>, cudaFuncAttributeMaxDynamicSharedMemorySize, SMB);

    // 0: weight prep
    split_all_kernel<<<2048, 256>>>(tm_value_w, tm_recept_w, sa_q_w, sa_k_w,
                                    sa_v_w, sa_o_w, tm_out_w, cm_recept_w,
                                    cm_key_w, cm_value_w,
                                    sa_q_b, sa_k_b, sa_v_b, bias);

    // 1: fused norm1 + mix1
    normmix_kernel<<<N_, 256>>>(x, norm1_w, tm_mix_v, tm_mix_r,
                                x1h, x1l,
                                xabh, xabl, xabh + (long long)N_*D_, xabl + (long long)N_*D_);

    // 2: MEGA1 — z=0: x1@[qk;sv] -> qk planes + Vsa;  z=1: xa@wv -> v;  z=2: xb@wr -> r
    gemm_mma<EMEGA1><<<dim3(9,64,3), 256, SMB>>>(
        x1h, x1l, D_, wqksvh, wqksvl, D_,
        bias, nullptr, nullptr,
        Vsa, qkh, qkl, 1152, D_, 1.f,
        (long long)N_*D_, (long long)D_*D_, 0,
        xabh, xabl, wvrh, wvrl, vr);

    // 3: scores = Q @ K^T / 8
    gemm_mma<EF32><<<dim3(32,32,2), 256, SMB>>>(qkh, qkl, 128, qkh + 64, qkl + 64, 128,
        nullptr, nullptr, nullptr, sc, nullptr, nullptr, S_, 64, 0.125f,
        (long long)S_*128, (long long)S_*128, (long long)S_*S_,
        nullptr, nullptr, nullptr, nullptr, nullptr);

    // 4: topk + softmax + gather
    topk_attn_kernel<<<N_, 256>>>(sc, Vsa, aph, apl);

    // 5: rkv = sigmoid(r)*(ap@o_w^T + o_b + v)
    gemm_mma<ERKV><<<dim3(8,64,1), 256, SMB>>>(aph, apl, D_, woh, wol, D_,
        sa_o_b, vr, vr + (long long)N_*D_, nullptr, rkh, rkl, D_, D_, 1.f, 0, 0, 0,
        nullptr, nullptr, nullptr, nullptr, nullptr);
    // 6: xmid = x + rkv@tm_out^T
    gemm_mma<EADD><<<dim3(8,64,1), 256, SMB>>>(rkh, rkl, D_, wtoh, wtol, D_,
        nullptr, x, nullptr, xmid, nullptr, nullptr, D_, D_, 1.f, 0, 0, 0,
        nullptr, nullptr, nullptr, nullptr, nullptr);

    // 7: fused norm2 + mix2
    normmix_kernel<<<N_, 256>>>(xmid, norm2_w, cm_mix_k, cm_mix_r,
                                nullptr, nullptr,
                                xabh, xabl, xabh + (long long)N_*D_, xabl + (long long)N_*D_);

    // 8: MEGA2 — z<4: kc slab z = relu(xa@ck_z^T)^2 planes;  z=4: r2 = xb@cr^T
    gemm_mma<EMEGA2><<<dim3(8,64,5), 256, SMB>>>(
        xabh, xabl, D_, wckcrh, wckcrl, D_,
        nullptr, nullptr, nullptr,
        r2, kch, kcl, DI_, D_, 1.f,
        0, 0, 0,
        xabh + (long long)N_*D_, xabl + (long long)N_*D_, nullptr, nullptr, nullptr);

    // 9: out = xmid + sigmoid(r2)*(kc@cv^T)
    gemm_mma<ECMFIN><<<dim3(8,64,1), 256, SMB>>>(kch, kcl, DI_, wcvh, wcvl, DI_,
        nullptr, xmid, r2, out, nullptr, nullptr, D_, DI_, 1.f, 0, 0, 0,
        nullptr, nullptr, nullptr, nullptr, nullptr);
}